// round 1
// baseline (speedup 1.0000x reference)
#include <cuda_runtime.h>
#include <cuda_bf16.h>
#include <cstddef>

// Problem constants
#define NLAYERS 2
#define BB 4
#define LL 2048
#define DD 512
#define NN 16
#define OO 512
#define MM (BB * LL)   // 8192 rows

// ---------------- scratch buffers (no allocation allowed) ----------------
__device__ float g_dt[MM * DD];   // softplus(dt) per layer
__device__ float g_bc[MM * 2 * NN]; // [row][32]: cols 0..15 = Bm, 16..31 = Cm
__device__ float g_y[MM * DD];    // scan output (post-gelu)
__device__ float g_y2[MM * DD];   // mix GEMM output (pre-LN)
__device__ float g_hA[MM * DD];   // layer outputs
__device__ float g_hB[MM * DD];

// ---------------- helpers ----------------
__device__ __forceinline__ float softplus_f(float v) {
    // numerically stable: max(v,0) + log1p(exp(-|v|))
    return fmaxf(v, 0.f) + log1pf(expf(-fabsf(v)));
}

__device__ __forceinline__ float gelu_f(float v) {
    return 0.5f * v * (1.f + erff(v * 0.70710678118654752440f));
}

// ---------------- generic SGEMM: C = A[M,K] @ W[K,Nc] + bias ----------------
// EPI: 0 = bias only, 1 = bias + softplus
#define TM 64
#define TN 64
#define TK 16

template <int EPI>
__global__ void gemm_kernel(const float* __restrict__ A,
                            const float* __restrict__ W,
                            const float* __restrict__ bias,
                            float* __restrict__ C,
                            int Mdim, int Ndim, int Kdim) {
    __shared__ float As[TK][TM];
    __shared__ float Ws[TK][TN];

    const int tid = threadIdx.x;            // 0..255
    const int tx = tid & 15;                // col group
    const int ty = tid >> 4;                // row group
    const int m0 = blockIdx.y * TM;
    const int n0 = blockIdx.x * TN;

    // A-tile load mapping: each thread loads a float4 (4 consecutive k)
    const int aRow = tid >> 2;              // 0..63
    const int aK4  = (tid & 3) * 4;         // 0,4,8,12
    // W-tile load mapping: each thread loads a float4 (4 consecutive n)
    const int wK  = tid >> 4;               // 0..15
    const int wN4 = (tid & 15) * 4;         // 0..60

    float acc[4][4];
#pragma unroll
    for (int i = 0; i < 4; i++)
#pragma unroll
        for (int j = 0; j < 4; j++) acc[i][j] = 0.f;

    for (int k0 = 0; k0 < Kdim; k0 += TK) {
        float4 av = *(const float4*)(A + (size_t)(m0 + aRow) * Kdim + k0 + aK4);
        As[aK4 + 0][aRow] = av.x;
        As[aK4 + 1][aRow] = av.y;
        As[aK4 + 2][aRow] = av.z;
        As[aK4 + 3][aRow] = av.w;
        float4 wv = *(const float4*)(W + (size_t)(k0 + wK) * Ndim + n0 + wN4);
        *(float4*)&Ws[wK][wN4] = wv;
        __syncthreads();

#pragma unroll
        for (int kk = 0; kk < TK; kk++) {
            float a4[4], b4[4];
#pragma unroll
            for (int i = 0; i < 4; i++) a4[i] = As[kk][ty * 4 + i];
#pragma unroll
            for (int j = 0; j < 4; j++) b4[j] = Ws[kk][tx * 4 + j];
#pragma unroll
            for (int i = 0; i < 4; i++)
#pragma unroll
                for (int j = 0; j < 4; j++) acc[i][j] = fmaf(a4[i], b4[j], acc[i][j]);
        }
        __syncthreads();
    }

    // epilogue
#pragma unroll
    for (int i = 0; i < 4; i++) {
        const int row = m0 + ty * 4 + i;
        const int col = n0 + tx * 4;
        float4 o;
        float v0 = acc[i][0] + bias[col + 0];
        float v1 = acc[i][1] + bias[col + 1];
        float v2 = acc[i][2] + bias[col + 2];
        float v3 = acc[i][3] + bias[col + 3];
        if (EPI == 1) {
            v0 = softplus_f(v0); v1 = softplus_f(v1);
            v2 = softplus_f(v2); v3 = softplus_f(v3);
        }
        o.x = v0; o.y = v1; o.z = v2; o.w = v3;
        *(float4*)(C + (size_t)row * Ndim + col) = o;
    }
}

// ---------------- B/C projection: [M,512] @ [512,16] x2 ----------------
// block = 256 threads = 8 rows x 32 lanes (lane<16 -> Bm, lane>=16 -> Cm)
__global__ void bc_kernel(const float* __restrict__ X,
                          const float* __restrict__ WB, const float* __restrict__ bB,
                          const float* __restrict__ WC, const float* __restrict__ bC,
                          float* __restrict__ BC) {
    __shared__ float xs[8][DD];
    const int tid = threadIdx.x;
    const int row0 = blockIdx.x * 8;

    // stage 8 input rows (4096 floats) via float4
    for (int i = tid; i < 8 * (DD / 4); i += 256) {
        int r = i >> 7;            // DD/4 = 128 float4 per row
        int c4 = i & 127;
        ((float4*)xs[r])[c4] = ((const float4*)(X + (size_t)(row0 + r) * DD))[c4];
    }
    __syncthreads();

    const int r = tid >> 5;
    const int c = tid & 31;
    const int n = c & 15;
    const float* Wp = (c < 16) ? WB : WC;
    float acc = (c < 16) ? bB[n] : bC[n];
    const float* xr = xs[r];
#pragma unroll 8
    for (int k = 0; k < DD; k++) acc = fmaf(xr[k], Wp[k * NN + n], acc);
    BC[(size_t)(row0 + r) * 32 + c] = acc;
}

// ---------------- fused discretize + scan + C-contract + skip + GELU ----------------
// grid = (D/16, B), block = 256 = 16 d-lanes x 16 n-lanes
__global__ void scan_kernel(const float* __restrict__ X,
                            const float* __restrict__ DT,
                            const float* __restrict__ BC,
                            const float* __restrict__ A_log,
                            const float* __restrict__ Dskip,
                            float* __restrict__ Y) {
    const int tid = threadIdx.x;
    const int n  = tid & 15;
    const int dl = tid >> 4;
    const int d  = blockIdx.x * 16 + dl;
    const int b  = blockIdx.y;

    const float Acoef = -expf(A_log[d * NN + n]);
    const float dsk = Dskip[d];
    float h = 0.f;

    const float* Xb  = X  + (size_t)b * LL * DD;
    const float* DTb = DT + (size_t)b * LL * DD;
    const float* BCb = BC + (size_t)b * LL * 32;
    float*       Yb  = Y  + (size_t)b * LL * DD;

    // prefetch l = 0
    float dtv = DTb[d];
    float xv  = Xb[d];
    float Bv  = BCb[n];
    float Cv  = BCb[16 + n];

    for (int l = 0; l < LL; l++) {
        // prefetch next iteration
        float dtv_n = 0.f, xv_n = 0.f, Bv_n = 0.f, Cv_n = 0.f;
        if (l + 1 < LL) {
            dtv_n = DTb[(size_t)(l + 1) * DD + d];
            xv_n  = Xb [(size_t)(l + 1) * DD + d];
            Bv_n  = BCb[(l + 1) * 32 + n];
            Cv_n  = BCb[(l + 1) * 32 + 16 + n];
        }
        const float a = expf(dtv * Acoef);
        h = fmaf(a, h, dtv * xv * Bv);
        float p = Cv * h;
        p += __shfl_xor_sync(0xffffffffu, p, 8, 16);
        p += __shfl_xor_sync(0xffffffffu, p, 4, 16);
        p += __shfl_xor_sync(0xffffffffu, p, 2, 16);
        p += __shfl_xor_sync(0xffffffffu, p, 1, 16);
        if (n == 0) {
            float y = fmaf(dsk, xv, p);
            Yb[(size_t)l * DD + d] = gelu_f(y);
        }
        dtv = dtv_n; xv = xv_n; Bv = Bv_n; Cv = Cv_n;
    }
}

// ---------------- layernorm + residual ----------------
// grid = M rows, block = 128 threads (4 elems each)
__global__ void ln_res_kernel(const float* __restrict__ Hin,
                              const float* __restrict__ Y2,
                              const float* __restrict__ g,
                              const float* __restrict__ bb,
                              float* __restrict__ Hout) {
    __shared__ float red[4];
    const int row = blockIdx.x;
    const int tid = threadIdx.x;
    const float* yr = Y2 + (size_t)row * DD;

    float v[4];
    float s = 0.f;
#pragma unroll
    for (int j = 0; j < 4; j++) { v[j] = yr[tid + j * 128]; s += v[j]; }

    // block reduce sum
#pragma unroll
    for (int o = 16; o > 0; o >>= 1) s += __shfl_xor_sync(0xffffffffu, s, o);
    if ((tid & 31) == 0) red[tid >> 5] = s;
    __syncthreads();
    const float mean = (red[0] + red[1] + red[2] + red[3]) * (1.f / DD);
    __syncthreads();

    float sq = 0.f;
#pragma unroll
    for (int j = 0; j < 4; j++) { float dlt = v[j] - mean; sq += dlt * dlt; }
#pragma unroll
    for (int o = 16; o > 0; o >>= 1) sq += __shfl_xor_sync(0xffffffffu, sq, o);
    if ((tid & 31) == 0) red[tid >> 5] = sq;
    __syncthreads();
    const float var = (red[0] + red[1] + red[2] + red[3]) * (1.f / DD);
    const float rstd = rsqrtf(var + 1e-5f);

#pragma unroll
    for (int j = 0; j < 4; j++) {
        const int col = tid + j * 128;
        float o = (v[j] - mean) * rstd * g[col] + bb[col];
        Hout[(size_t)row * DD + col] = Hin[(size_t)row * DD + col] + o;
    }
}

// ---------------- launch ----------------
extern "C" void kernel_launch(void* const* d_in, const int* in_sizes, int n_in,
                              void* d_out, int out_size) {
    const float* x      = (const float*)d_in[0];
    const float* A_log  = (const float*)d_in[1];
    const float* W_B    = (const float*)d_in[2];
    const float* b_B    = (const float*)d_in[3];
    const float* W_C    = (const float*)d_in[4];
    const float* b_C    = (const float*)d_in[5];
    const float* W_dt   = (const float*)d_in[6];
    const float* b_dt   = (const float*)d_in[7];
    const float* D_skip = (const float*)d_in[8];
    const float* W_mix  = (const float*)d_in[9];
    const float* b_mix  = (const float*)d_in[10];
    const float* ln_g   = (const float*)d_in[11];
    const float* ln_b   = (const float*)d_in[12];
    const float* W_dec  = (const float*)d_in[13];
    const float* b_dec  = (const float*)d_in[14];
    float* out = (float*)d_out;

    float *p_dt, *p_bc, *p_y, *p_y2, *p_hA, *p_hB;
    cudaGetSymbolAddress((void**)&p_dt, g_dt);
    cudaGetSymbolAddress((void**)&p_bc, g_bc);
    cudaGetSymbolAddress((void**)&p_y,  g_y);
    cudaGetSymbolAddress((void**)&p_y2, g_y2);
    cudaGetSymbolAddress((void**)&p_hA, g_hA);
    cudaGetSymbolAddress((void**)&p_hB, g_hB);

    const dim3 gemmGrid(DD / TN, MM / TM);   // (8, 128)
    const dim3 scanGrid(DD / 16, BB);        // (32, 4)

    const float* hin = x;
    float* houts[2] = { p_hA, p_hB };

    for (int l = 0; l < NLAYERS; l++) {
        // dt = softplus(hin @ W_dt + b_dt)
        gemm_kernel<1><<<gemmGrid, 256>>>(hin, W_dt + (size_t)l * DD * DD,
                                          b_dt + l * DD, p_dt, MM, DD, DD);
        // Bm, Cm
        bc_kernel<<<MM / 8, 256>>>(hin, W_B + (size_t)l * DD * NN, b_B + l * NN,
                                   W_C + (size_t)l * DD * NN, b_C + l * NN, p_bc);
        // fused scan + C-contraction + D-skip + GELU
        scan_kernel<<<scanGrid, 256>>>(hin, p_dt, p_bc,
                                       A_log + (size_t)l * DD * NN,
                                       D_skip + l * DD, p_y);
        // mix
        gemm_kernel<0><<<gemmGrid, 256>>>(p_y, W_mix + (size_t)l * DD * DD,
                                          b_mix + l * DD, p_y2, MM, DD, DD);
        // LN + residual
        ln_res_kernel<<<MM, 128>>>(hin, p_y2, ln_g + l * DD, ln_b + l * DD, houts[l]);
        hin = houts[l];
    }

    // decoder
    gemm_kernel<0><<<gemmGrid, 256>>>(hin, W_dec, b_dec, out, MM, OO, DD);
}

// round 2
// speedup vs baseline: 2.4666x; 2.4666x over previous
#include <cuda_runtime.h>
#include <cuda_bf16.h>
#include <cstddef>
#include <cstdint>

// Problem constants
#define NLAYERS 2
#define BB 4
#define LL 2048
#define DD 512
#define NN 16
#define OO 512
#define MM (BB * LL)   // 8192 rows

// ---------------- scratch buffers (no allocation allowed) ----------------
__device__ float g_dt[MM * DD];     // softplus(dt) per layer
__device__ float g_bc[MM * 2 * NN]; // [row][32]: cols 0..15 = Bm, 16..31 = Cm
__device__ float g_y[MM * DD];      // scan output (post-gelu)
__device__ float g_y2[MM * DD];     // mix GEMM output (pre-LN)
__device__ float g_hA[MM * DD];     // layer outputs
__device__ float g_hB[MM * DD];

// ---------------- helpers ----------------
__device__ __forceinline__ float softplus_f(float v) {
    return fmaxf(v, 0.f) + log1pf(__expf(-fabsf(v)));
}

__device__ __forceinline__ float gelu_f(float v) {
    return 0.5f * v * (1.f + erff(v * 0.70710678118654752440f));
}

__device__ __forceinline__ uint32_t f2tf32(float f) {
    uint32_t u;
    asm("cvt.rna.tf32.f32 %0, %1;" : "=r"(u) : "f"(f));
    return u;
}

__device__ __forceinline__ void cp_async16(void* smem, const void* gmem) {
    uint32_t s = (uint32_t)__cvta_generic_to_shared(smem);
    asm volatile("cp.async.cg.shared.global [%0], [%1], 16;" :: "r"(s), "l"(gmem));
}
__device__ __forceinline__ void cp_commit() {
    asm volatile("cp.async.commit_group;");
}
template <int N>
__device__ __forceinline__ void cp_wait() {
    asm volatile("cp.async.wait_group %0;" :: "n"(N));
}

__device__ __forceinline__ void mma_tf32(float4& d,
                                         const uint32_t* a,
                                         uint32_t b0, uint32_t b1,
                                         const float4& c) {
    asm volatile(
        "mma.sync.aligned.m16n8k8.row.col.f32.tf32.tf32.f32 "
        "{%0,%1,%2,%3}, {%4,%5,%6,%7}, {%8,%9}, {%10,%11,%12,%13};"
        : "=f"(d.x), "=f"(d.y), "=f"(d.z), "=f"(d.w)
        : "r"(a[0]), "r"(a[1]), "r"(a[2]), "r"(a[3]),
          "r"(b0), "r"(b1),
          "f"(c.x), "f"(c.y), "f"(c.z), "f"(c.w));
}

// ---------------- tensor-core GEMM: C = A[M,512] @ W[512,512] + bias ----------------
// CTA tile 128x64, k-tile 32, 8 warps as 4(M)x2(N), warp tile 32x32.
// smem: As[2][128][36] + Bs[2][32][72]  = 55296 bytes dynamic
#define AS_STRIDE 36
#define BS_STRIDE 72
#define AS_TILE (128 * AS_STRIDE)
#define BS_TILE (32 * BS_STRIDE)
#define GEMM_SMEM_BYTES ((2 * AS_TILE + 2 * BS_TILE) * 4)

// EPI: 0 = bias only, 1 = bias + softplus
template <int EPI>
__global__ void gemm_tc(const float* __restrict__ A,
                        const float* __restrict__ W,
                        const float* __restrict__ bias,
                        float* __restrict__ C) {
    extern __shared__ float smem[];
    float* As = smem;                  // 2 * 128 * 36
    float* Bs = smem + 2 * AS_TILE;    // 2 * 32 * 72

    const int tid  = threadIdx.x;
    const int lane = tid & 31;
    const int warp = tid >> 5;
    const int g    = lane >> 2;   // groupID 0..7
    const int tig  = lane & 3;    // thread in group 0..3
    const int mBase = (warp >> 1) * 32;   // 0,32,64,96
    const int nBase = (warp & 1) * 32;    // 0,32

    const int m0 = blockIdx.y * 128;
    const int n0 = blockIdx.x * 64;

    float4 acc[2][4];
#pragma unroll
    for (int t = 0; t < 2; t++)
#pragma unroll
        for (int j = 0; j < 4; j++) acc[t][j] = make_float4(0.f, 0.f, 0.f, 0.f);

    // tile loader
    auto load_tile = [&](int kt, int stage) {
        float* as = As + stage * AS_TILE;
        float* bs = Bs + stage * BS_TILE;
#pragma unroll
        for (int i = 0; i < 4; i++) {
            int c = tid + 256 * i;           // 0..1023
            int row = c >> 3;                // 0..127
            int kc = (c & 7) * 4;            // 0..28
            cp_async16(as + row * AS_STRIDE + kc,
                       A + (size_t)(m0 + row) * 512 + kt * 32 + kc);
        }
#pragma unroll
        for (int i = 0; i < 2; i++) {
            int c = tid + 256 * i;           // 0..511
            int row = c >> 4;                // 0..31
            int nc = (c & 15) * 4;           // 0..60
            cp_async16(bs + row * BS_STRIDE + nc,
                       W + (size_t)(kt * 32 + row) * 512 + n0 + nc);
        }
        cp_commit();
    };

    load_tile(0, 0);

    const int NKT = 512 / 32;  // 16
    for (int kt = 0; kt < NKT; kt++) {
        if (kt + 1 < NKT) load_tile(kt + 1, (kt + 1) & 1);
        if (kt + 1 < NKT) cp_wait<1>(); else cp_wait<0>();
        __syncthreads();

        const float* as = As + (kt & 1) * AS_TILE;
        const float* bs = Bs + (kt & 1) * BS_TILE;

#pragma unroll
        for (int s = 0; s < 4; s++) {
            const int k = s * 8 + tig;
            uint32_t afr[2][4];
#pragma unroll
            for (int t = 0; t < 2; t++) {
                const int r = mBase + 16 * t + g;
                afr[t][0] = f2tf32(as[r * AS_STRIDE + k]);
                afr[t][1] = f2tf32(as[(r + 8) * AS_STRIDE + k]);
                afr[t][2] = f2tf32(as[r * AS_STRIDE + k + 4]);
                afr[t][3] = f2tf32(as[(r + 8) * AS_STRIDE + k + 4]);
            }
#pragma unroll
            for (int j = 0; j < 4; j++) {
                uint32_t b0 = f2tf32(bs[k * BS_STRIDE + nBase + 8 * j + g]);
                uint32_t b1 = f2tf32(bs[(k + 4) * BS_STRIDE + nBase + 8 * j + g]);
                mma_tf32(acc[0][j], afr[0], b0, b1, acc[0][j]);
                mma_tf32(acc[1][j], afr[1], b0, b1, acc[1][j]);
            }
        }
        __syncthreads();
    }

    // epilogue
#pragma unroll
    for (int t = 0; t < 2; t++) {
#pragma unroll
        for (int j = 0; j < 4; j++) {
            const int row = m0 + mBase + 16 * t + g;
            const int col = n0 + nBase + 8 * j + tig * 2;
            float b0 = bias[col], b1 = bias[col + 1];
            float v0 = acc[t][j].x + b0;
            float v1 = acc[t][j].y + b1;
            float v2 = acc[t][j].z + b0;
            float v3 = acc[t][j].w + b1;
            if (EPI == 1) {
                v0 = softplus_f(v0); v1 = softplus_f(v1);
                v2 = softplus_f(v2); v3 = softplus_f(v3);
            }
            *(float2*)(C + (size_t)row * 512 + col) = make_float2(v0, v1);
            *(float2*)(C + (size_t)(row + 8) * 512 + col) = make_float2(v2, v3);
        }
    }
}

// ---------------- B/C projection: [M,512] @ [512,16] x2 ----------------
__global__ void bc_kernel(const float* __restrict__ X,
                          const float* __restrict__ WB, const float* __restrict__ bB,
                          const float* __restrict__ WC, const float* __restrict__ bC,
                          float* __restrict__ BC) {
    __shared__ float xs[8][DD];
    const int tid = threadIdx.x;
    const int row0 = blockIdx.x * 8;

    for (int i = tid; i < 8 * (DD / 4); i += 256) {
        int r = i >> 7;
        int c4 = i & 127;
        ((float4*)xs[r])[c4] = ((const float4*)(X + (size_t)(row0 + r) * DD))[c4];
    }
    __syncthreads();

    const int r = tid >> 5;
    const int c = tid & 31;
    const int n = c & 15;
    const float* Wp = (c < 16) ? WB : WC;
    float acc = (c < 16) ? bB[n] : bC[n];
    const float* xr = xs[r];
#pragma unroll 8
    for (int k = 0; k < DD; k++) acc = fmaf(xr[k], __ldg(Wp + k * NN + n), acc);
    BC[(size_t)(row0 + r) * 32 + c] = acc;
}

// ---------------- fused discretize + scan + C-contract + skip + GELU ----------------
// grid = (D/16, B), block = 256 = 16 d-lanes x 16 n-lanes, 4 timesteps per iter
__global__ void scan_kernel(const float* __restrict__ X,
                            const float* __restrict__ DT,
                            const float* __restrict__ BC,
                            const float* __restrict__ A_log,
                            const float* __restrict__ Dskip,
                            float* __restrict__ Y) {
    const int tid = threadIdx.x;
    const int n  = tid & 15;
    const int dl = tid >> 4;
    const int d  = blockIdx.x * 16 + dl;
    const int b  = blockIdx.y;

    const float Acoef = -__expf(A_log[d * NN + n]);
    const float dsk = Dskip[d];
    float h = 0.f;

    const float* Xb  = X  + (size_t)b * LL * DD;
    const float* DTb = DT + (size_t)b * LL * DD;
    const float* BCb = BC + (size_t)b * LL * 32;
    float*       Yb  = Y  + (size_t)b * LL * DD;

    float dtc[4], xc[4], Bc[4], Cc[4];
#pragma unroll
    for (int u = 0; u < 4; u++) {
        dtc[u] = DTb[(size_t)u * DD + d];
        xc[u]  = Xb [(size_t)u * DD + d];
        Bc[u]  = BCb[u * 32 + n];
        Cc[u]  = BCb[u * 32 + 16 + n];
    }

    for (int l0 = 0; l0 < LL; l0 += 4) {
        float dtn[4], xn[4], Bn[4], Cn[4];
#pragma unroll
        for (int u = 0; u < 4; u++) {
            int ln = l0 + 4 + u;
            if (ln >= LL) ln = 0;   // harmless valid read on last batch
            dtn[u] = DTb[(size_t)ln * DD + d];
            xn[u]  = Xb [(size_t)ln * DD + d];
            Bn[u]  = BCb[ln * 32 + n];
            Cn[u]  = BCb[ln * 32 + 16 + n];
        }

        float p[4];
#pragma unroll
        for (int u = 0; u < 4; u++) {
            const float a = __expf(dtc[u] * Acoef);
            h = fmaf(a, h, dtc[u] * xc[u] * Bc[u]);
            p[u] = Cc[u] * h;
        }
        // 4 independent reduction trees -> shfl latency pipelined
#pragma unroll
        for (int u = 0; u < 4; u++) p[u] += __shfl_xor_sync(0xffffffffu, p[u], 8, 16);
#pragma unroll
        for (int u = 0; u < 4; u++) p[u] += __shfl_xor_sync(0xffffffffu, p[u], 4, 16);
#pragma unroll
        for (int u = 0; u < 4; u++) p[u] += __shfl_xor_sync(0xffffffffu, p[u], 2, 16);
#pragma unroll
        for (int u = 0; u < 4; u++) p[u] += __shfl_xor_sync(0xffffffffu, p[u], 1, 16);

        if (n == 0) {
#pragma unroll
            for (int u = 0; u < 4; u++) {
                float y = fmaf(dsk, xc[u], p[u]);
                Yb[(size_t)(l0 + u) * DD + d] = gelu_f(y);
            }
        }
#pragma unroll
        for (int u = 0; u < 4; u++) {
            dtc[u] = dtn[u]; xc[u] = xn[u]; Bc[u] = Bn[u]; Cc[u] = Cn[u];
        }
    }
}

// ---------------- layernorm + residual ----------------
__global__ void ln_res_kernel(const float* __restrict__ Hin,
                              const float* __restrict__ Y2,
                              const float* __restrict__ g,
                              const float* __restrict__ bb,
                              float* __restrict__ Hout) {
    __shared__ float red[4];
    const int row = blockIdx.x;
    const int tid = threadIdx.x;
    const float* yr = Y2 + (size_t)row * DD;

    float v[4];
    float s = 0.f;
#pragma unroll
    for (int j = 0; j < 4; j++) { v[j] = yr[tid + j * 128]; s += v[j]; }

#pragma unroll
    for (int o = 16; o > 0; o >>= 1) s += __shfl_xor_sync(0xffffffffu, s, o);
    if ((tid & 31) == 0) red[tid >> 5] = s;
    __syncthreads();
    const float mean = (red[0] + red[1] + red[2] + red[3]) * (1.f / DD);
    __syncthreads();

    float sq = 0.f;
#pragma unroll
    for (int j = 0; j < 4; j++) { float dlt = v[j] - mean; sq += dlt * dlt; }
#pragma unroll
    for (int o = 16; o > 0; o >>= 1) sq += __shfl_xor_sync(0xffffffffu, sq, o);
    if ((tid & 31) == 0) red[tid >> 5] = sq;
    __syncthreads();
    const float var = (red[0] + red[1] + red[2] + red[3]) * (1.f / DD);
    const float rstd = rsqrtf(var + 1e-5f);

#pragma unroll
    for (int j = 0; j < 4; j++) {
        const int col = tid + j * 128;
        float o = (v[j] - mean) * rstd * g[col] + bb[col];
        Hout[(size_t)row * DD + col] = Hin[(size_t)row * DD + col] + o;
    }
}

// ---------------- launch ----------------
extern "C" void kernel_launch(void* const* d_in, const int* in_sizes, int n_in,
                              void* d_out, int out_size) {
    const float* x      = (const float*)d_in[0];
    const float* A_log  = (const float*)d_in[1];
    const float* W_B    = (const float*)d_in[2];
    const float* b_B    = (const float*)d_in[3];
    const float* W_C    = (const float*)d_in[4];
    const float* b_C    = (const float*)d_in[5];
    const float* W_dt   = (const float*)d_in[6];
    const float* b_dt   = (const float*)d_in[7];
    const float* D_skip = (const float*)d_in[8];
    const float* W_mix  = (const float*)d_in[9];
    const float* b_mix  = (const float*)d_in[10];
    const float* ln_g   = (const float*)d_in[11];
    const float* ln_b   = (const float*)d_in[12];
    const float* W_dec  = (const float*)d_in[13];
    const float* b_dec  = (const float*)d_in[14];
    float* out = (float*)d_out;

    float *p_dt, *p_bc, *p_y, *p_y2, *p_hA, *p_hB;
    cudaGetSymbolAddress((void**)&p_dt, g_dt);
    cudaGetSymbolAddress((void**)&p_bc, g_bc);
    cudaGetSymbolAddress((void**)&p_y,  g_y);
    cudaGetSymbolAddress((void**)&p_y2, g_y2);
    cudaGetSymbolAddress((void**)&p_hA, g_hA);
    cudaGetSymbolAddress((void**)&p_hB, g_hB);

    cudaFuncSetAttribute(gemm_tc<0>, cudaFuncAttributeMaxDynamicSharedMemorySize,
                         GEMM_SMEM_BYTES);
    cudaFuncSetAttribute(gemm_tc<1>, cudaFuncAttributeMaxDynamicSharedMemorySize,
                         GEMM_SMEM_BYTES);

    const dim3 gemmGrid(DD / 64, MM / 128);  // (8, 64)
    const dim3 scanGrid(DD / 16, BB);        // (32, 4)

    const float* hin = x;
    float* houts[2] = { p_hA, p_hB };

    for (int l = 0; l < NLAYERS; l++) {
        // dt = softplus(hin @ W_dt + b_dt)
        gemm_tc<1><<<gemmGrid, 256, GEMM_SMEM_BYTES>>>(
            hin, W_dt + (size_t)l * DD * DD, b_dt + l * DD, p_dt);
        // Bm, Cm
        bc_kernel<<<MM / 8, 256>>>(hin, W_B + (size_t)l * DD * NN, b_B + l * NN,
                                   W_C + (size_t)l * DD * NN, b_C + l * NN, p_bc);
        // fused scan + C-contraction + D-skip + GELU
        scan_kernel<<<scanGrid, 256>>>(hin, p_dt, p_bc,
                                       A_log + (size_t)l * DD * NN,
                                       D_skip + l * DD, p_y);
        // mix
        gemm_tc<0><<<gemmGrid, 256, GEMM_SMEM_BYTES>>>(
            p_y, W_mix + (size_t)l * DD * DD, b_mix + l * DD, p_y2);
        // LN + residual
        ln_res_kernel<<<MM, 128>>>(hin, p_y2, ln_g + l * DD, ln_b + l * DD, houts[l]);
        hin = houts[l];
    }

    // decoder
    gemm_tc<0><<<gemmGrid, 256, GEMM_SMEM_BYTES>>>(hin, W_dec, b_dec, out);
}

// round 3
// speedup vs baseline: 3.0288x; 1.2280x over previous
#include <cuda_runtime.h>
#include <cuda_bf16.h>
#include <cstddef>
#include <cstdint>

// Problem constants
#define NLAYERS 2
#define BB 4
#define LL 2048
#define DD 512
#define NN 16
#define OO 512
#define MM (BB * LL)   // 8192 rows

// scan chunking
#define NCH 16
#define CL (LL / NCH)  // 128

// ---------------- scratch buffers (no allocation allowed) ----------------
__device__ float g_dt[MM * DD];     // softplus(dt) per layer
__device__ float g_bc[MM * 2 * NN]; // [row][32]: 0..15 = Bm, 16..31 = Cm
__device__ float g_y[MM * DD];      // scan output (post-gelu)
__device__ float g_y2[MM * DD];     // mix GEMM output (pre-LN)
__device__ float g_hA[MM * DD];     // layer outputs
__device__ float g_hB[MM * DD];
__device__ float g_cA[BB * NCH * DD * NN];  // chunk A-product
__device__ float g_cH[BB * NCH * DD * NN];  // chunk local h_end
__device__ float g_ci[BB * NCH * DD * NN];  // chunk initial h

// ---------------- helpers ----------------
__device__ __forceinline__ float softplus_f(float v) {
    return fmaxf(v, 0.f) + log1pf(__expf(-fabsf(v)));
}

__device__ __forceinline__ float gelu_f(float v) {
    return 0.5f * v * (1.f + erff(v * 0.70710678118654752440f));
}

__device__ __forceinline__ uint32_t f2tf32(float f) {
    uint32_t u;
    asm("cvt.rna.tf32.f32 %0, %1;" : "=r"(u) : "f"(f));
    return u;
}

__device__ __forceinline__ void cp_async16(void* smem, const void* gmem) {
    uint32_t s = (uint32_t)__cvta_generic_to_shared(smem);
    asm volatile("cp.async.cg.shared.global [%0], [%1], 16;" :: "r"(s), "l"(gmem));
}
__device__ __forceinline__ void cp_commit() {
    asm volatile("cp.async.commit_group;");
}
template <int N>
__device__ __forceinline__ void cp_wait() {
    asm volatile("cp.async.wait_group %0;" :: "n"(N));
}

__device__ __forceinline__ void mma_tf32(float4& d,
                                         const uint32_t* a,
                                         uint32_t b0, uint32_t b1,
                                         const float4& c) {
    asm volatile(
        "mma.sync.aligned.m16n8k8.row.col.f32.tf32.tf32.f32 "
        "{%0,%1,%2,%3}, {%4,%5,%6,%7}, {%8,%9}, {%10,%11,%12,%13};"
        : "=f"(d.x), "=f"(d.y), "=f"(d.z), "=f"(d.w)
        : "r"(a[0]), "r"(a[1]), "r"(a[2]), "r"(a[3]),
          "r"(b0), "r"(b1),
          "f"(c.x), "f"(c.y), "f"(c.z), "f"(c.w));
}

// ---------------- tensor-core GEMM: C = A[M,512] @ W[512,512] + bias ----------------
#define AS_STRIDE 36
#define BS_STRIDE 72
#define AS_TILE (128 * AS_STRIDE)
#define BS_TILE (32 * BS_STRIDE)
#define GEMM_SMEM_BYTES ((2 * AS_TILE + 2 * BS_TILE) * 4)

template <int EPI>
__global__ void gemm_tc(const float* __restrict__ A,
                        const float* __restrict__ W,
                        const float* __restrict__ bias,
                        float* __restrict__ C) {
    extern __shared__ float smem[];
    float* As = smem;
    float* Bs = smem + 2 * AS_TILE;

    const int tid  = threadIdx.x;
    const int lane = tid & 31;
    const int warp = tid >> 5;
    const int g    = lane >> 2;
    const int tig  = lane & 3;
    const int mBase = (warp >> 1) * 32;
    const int nBase = (warp & 1) * 32;

    const int m0 = blockIdx.y * 128;
    const int n0 = blockIdx.x * 64;

    float4 acc[2][4];
#pragma unroll
    for (int t = 0; t < 2; t++)
#pragma unroll
        for (int j = 0; j < 4; j++) acc[t][j] = make_float4(0.f, 0.f, 0.f, 0.f);

    auto load_tile = [&](int kt, int stage) {
        float* as = As + stage * AS_TILE;
        float* bs = Bs + stage * BS_TILE;
#pragma unroll
        for (int i = 0; i < 4; i++) {
            int c = tid + 256 * i;
            int row = c >> 3;
            int kc = (c & 7) * 4;
            cp_async16(as + row * AS_STRIDE + kc,
                       A + (size_t)(m0 + row) * 512 + kt * 32 + kc);
        }
#pragma unroll
        for (int i = 0; i < 2; i++) {
            int c = tid + 256 * i;
            int row = c >> 4;
            int nc = (c & 15) * 4;
            cp_async16(bs + row * BS_STRIDE + nc,
                       W + (size_t)(kt * 32 + row) * 512 + n0 + nc);
        }
        cp_commit();
    };

    load_tile(0, 0);

    const int NKT = 512 / 32;
    for (int kt = 0; kt < NKT; kt++) {
        if (kt + 1 < NKT) load_tile(kt + 1, (kt + 1) & 1);
        if (kt + 1 < NKT) cp_wait<1>(); else cp_wait<0>();
        __syncthreads();

        const float* as = As + (kt & 1) * AS_TILE;
        const float* bs = Bs + (kt & 1) * BS_TILE;

#pragma unroll
        for (int s = 0; s < 4; s++) {
            const int k = s * 8 + tig;
            uint32_t afr[2][4];
#pragma unroll
            for (int t = 0; t < 2; t++) {
                const int r = mBase + 16 * t + g;
                afr[t][0] = f2tf32(as[r * AS_STRIDE + k]);
                afr[t][1] = f2tf32(as[(r + 8) * AS_STRIDE + k]);
                afr[t][2] = f2tf32(as[r * AS_STRIDE + k + 4]);
                afr[t][3] = f2tf32(as[(r + 8) * AS_STRIDE + k + 4]);
            }
#pragma unroll
            for (int j = 0; j < 4; j++) {
                uint32_t b0 = f2tf32(bs[k * BS_STRIDE + nBase + 8 * j + g]);
                uint32_t b1 = f2tf32(bs[(k + 4) * BS_STRIDE + nBase + 8 * j + g]);
                mma_tf32(acc[0][j], afr[0], b0, b1, acc[0][j]);
                mma_tf32(acc[1][j], afr[1], b0, b1, acc[1][j]);
            }
        }
        __syncthreads();
    }

#pragma unroll
    for (int t = 0; t < 2; t++) {
#pragma unroll
        for (int j = 0; j < 4; j++) {
            const int row = m0 + mBase + 16 * t + g;
            const int col = n0 + nBase + 8 * j + tig * 2;
            float b0 = bias[col], b1 = bias[col + 1];
            float v0 = acc[t][j].x + b0;
            float v1 = acc[t][j].y + b1;
            float v2 = acc[t][j].z + b0;
            float v3 = acc[t][j].w + b1;
            if (EPI == 1) {
                v0 = softplus_f(v0); v1 = softplus_f(v1);
                v2 = softplus_f(v2); v3 = softplus_f(v3);
            }
            *(float2*)(C + (size_t)row * 512 + col) = make_float2(v0, v1);
            *(float2*)(C + (size_t)(row + 8) * 512 + col) = make_float2(v2, v3);
        }
    }
}

// ---------------- B/C projection: [M,512] @ [512,16] x2 ----------------
__global__ void bc_kernel(const float* __restrict__ X,
                          const float* __restrict__ WB, const float* __restrict__ bB,
                          const float* __restrict__ WC, const float* __restrict__ bC,
                          float* __restrict__ BC) {
    __shared__ float xs[8][DD];
    const int tid = threadIdx.x;
    const int row0 = blockIdx.x * 8;

    for (int i = tid; i < 8 * (DD / 4); i += 256) {
        int r = i >> 7;
        int c4 = i & 127;
        ((float4*)xs[r])[c4] = ((const float4*)(X + (size_t)(row0 + r) * DD))[c4];
    }
    __syncthreads();

    const int r = tid >> 5;
    const int c = tid & 31;
    const int n = c & 15;
    const float* Wp = (c < 16) ? WB : WC;
    float acc = (c < 16) ? bB[n] : bC[n];
    const float* xr = xs[r];
#pragma unroll 8
    for (int k = 0; k < DD; k++) acc = fmaf(xr[k], __ldg(Wp + k * NN + n), acc);
    BC[(size_t)(row0 + r) * 32 + c] = acc;
}

// ---------------- scan pass 1: per-chunk carry (A_prod, h_end) ----------------
// grid = (D/16, NCH, B), block = 256 = 16 d x 16 n
__global__ void scan_carry(const float* __restrict__ X,
                           const float* __restrict__ DT,
                           const float* __restrict__ BC,
                           const float* __restrict__ A_log,
                           float* __restrict__ cA,
                           float* __restrict__ cH) {
    const int tid = threadIdx.x;
    const int n  = tid & 15;
    const int dl = tid >> 4;
    const int d  = blockIdx.x * 16 + dl;
    const int ch = blockIdx.y;
    const int b  = blockIdx.z;

    const float Acoef = -__expf(A_log[d * NN + n]);
    float h = 0.f, Ap = 1.f;

    const float* Xb  = X  + (size_t)b * LL * DD + (size_t)ch * CL * DD;
    const float* DTb = DT + (size_t)b * LL * DD + (size_t)ch * CL * DD;
    const float* BCb = BC + (size_t)b * LL * 32 + (size_t)ch * CL * 32;

#pragma unroll 4
    for (int l = 0; l < CL; l++) {
        const float dtv = DTb[(size_t)l * DD + d];
        const float xv  = Xb [(size_t)l * DD + d];
        const float Bv  = BCb[l * 32 + n];
        const float a = __expf(dtv * Acoef);
        h = fmaf(a, h, dtv * xv * Bv);
        Ap *= a;
    }
    const size_t o = ((size_t)(b * NCH + ch) * DD + d) * NN + n;
    cA[o] = Ap;
    cH[o] = h;
}

// ---------------- scan pass 2: sequential combine over chunks ----------------
// grid = BB*DD*NN/256 = 128 blocks
__global__ void carry_combine(const float* __restrict__ cA,
                              const float* __restrict__ cH,
                              float* __restrict__ ci) {
    const int t = blockIdx.x * 256 + threadIdx.x;   // 0..32767
    const int b = t >> 13;                           // /8192
    const int r = t & 8191;                          // (d*16+n)
    float h = 0.f;
#pragma unroll
    for (int c = 0; c < NCH; c++) {
        const size_t o = (size_t)(b * NCH + c) * (DD * NN) + r;
        ci[o] = h;
        h = fmaf(cA[o], h, cH[o]);
    }
}

// ---------------- scan pass 3: per-chunk full scan + C-contract + skip + GELU --
// grid = (D/16, NCH, B), block = 256
__global__ void scan_apply(const float* __restrict__ X,
                           const float* __restrict__ DT,
                           const float* __restrict__ BC,
                           const float* __restrict__ A_log,
                           const float* __restrict__ Dskip,
                           const float* __restrict__ ci,
                           float* __restrict__ Y) {
    const int tid = threadIdx.x;
    const int n  = tid & 15;
    const int dl = tid >> 4;
    const int d  = blockIdx.x * 16 + dl;
    const int ch = blockIdx.y;
    const int b  = blockIdx.z;

    const float Acoef = -__expf(A_log[d * NN + n]);
    const float dsk = Dskip[d];
    float h = ci[((size_t)(b * NCH + ch) * DD + d) * NN + n];

    const float* Xb  = X  + (size_t)b * LL * DD + (size_t)ch * CL * DD;
    const float* DTb = DT + (size_t)b * LL * DD + (size_t)ch * CL * DD;
    const float* BCb = BC + (size_t)b * LL * 32 + (size_t)ch * CL * 32;
    float*       Yb  = Y  + (size_t)b * LL * DD + (size_t)ch * CL * DD;

    for (int l0 = 0; l0 < CL; l0 += 4) {
        float dtc[4], xc[4], Bc[4], Cc[4];
#pragma unroll
        for (int u = 0; u < 4; u++) {
            const int l = l0 + u;
            dtc[u] = DTb[(size_t)l * DD + d];
            xc[u]  = Xb [(size_t)l * DD + d];
            Bc[u]  = BCb[l * 32 + n];
            Cc[u]  = BCb[l * 32 + 16 + n];
        }
        float p[4];
#pragma unroll
        for (int u = 0; u < 4; u++) {
            const float a = __expf(dtc[u] * Acoef);
            h = fmaf(a, h, dtc[u] * xc[u] * Bc[u]);
            p[u] = Cc[u] * h;
        }
#pragma unroll
        for (int u = 0; u < 4; u++) p[u] += __shfl_xor_sync(0xffffffffu, p[u], 8, 16);
#pragma unroll
        for (int u = 0; u < 4; u++) p[u] += __shfl_xor_sync(0xffffffffu, p[u], 4, 16);
#pragma unroll
        for (int u = 0; u < 4; u++) p[u] += __shfl_xor_sync(0xffffffffu, p[u], 2, 16);
#pragma unroll
        for (int u = 0; u < 4; u++) p[u] += __shfl_xor_sync(0xffffffffu, p[u], 1, 16);

        if (n == 0) {
#pragma unroll
            for (int u = 0; u < 4; u++) {
                float y = fmaf(dsk, xc[u], p[u]);
                Yb[(size_t)(l0 + u) * DD + d] = gelu_f(y);
            }
        }
    }
}

// ---------------- layernorm + residual ----------------
__global__ void ln_res_kernel(const float* __restrict__ Hin,
                              const float* __restrict__ Y2,
                              const float* __restrict__ g,
                              const float* __restrict__ bb,
                              float* __restrict__ Hout) {
    __shared__ float red[4];
    const int row = blockIdx.x;
    const int tid = threadIdx.x;
    const float* yr = Y2 + (size_t)row * DD;

    float v[4];
    float s = 0.f;
#pragma unroll
    for (int j = 0; j < 4; j++) { v[j] = yr[tid + j * 128]; s += v[j]; }

#pragma unroll
    for (int o = 16; o > 0; o >>= 1) s += __shfl_xor_sync(0xffffffffu, s, o);
    if ((tid & 31) == 0) red[tid >> 5] = s;
    __syncthreads();
    const float mean = (red[0] + red[1] + red[2] + red[3]) * (1.f / DD);
    __syncthreads();

    float sq = 0.f;
#pragma unroll
    for (int j = 0; j < 4; j++) { float dlt = v[j] - mean; sq += dlt * dlt; }
#pragma unroll
    for (int o = 16; o > 0; o >>= 1) sq += __shfl_xor_sync(0xffffffffu, sq, o);
    if ((tid & 31) == 0) red[tid >> 5] = sq;
    __syncthreads();
    const float var = (red[0] + red[1] + red[2] + red[3]) * (1.f / DD);
    const float rstd = rsqrtf(var + 1e-5f);

#pragma unroll
    for (int j = 0; j < 4; j++) {
        const int col = tid + j * 128;
        float o = (v[j] - mean) * rstd * g[col] + bb[col];
        Hout[(size_t)row * DD + col] = Hin[(size_t)row * DD + col] + o;
    }
}

// ---------------- launch ----------------
extern "C" void kernel_launch(void* const* d_in, const int* in_sizes, int n_in,
                              void* d_out, int out_size) {
    const float* x      = (const float*)d_in[0];
    const float* A_log  = (const float*)d_in[1];
    const float* W_B    = (const float*)d_in[2];
    const float* b_B    = (const float*)d_in[3];
    const float* W_C    = (const float*)d_in[4];
    const float* b_C    = (const float*)d_in[5];
    const float* W_dt   = (const float*)d_in[6];
    const float* b_dt   = (const float*)d_in[7];
    const float* D_skip = (const float*)d_in[8];
    const float* W_mix  = (const float*)d_in[9];
    const float* b_mix  = (const float*)d_in[10];
    const float* ln_g   = (const float*)d_in[11];
    const float* ln_b   = (const float*)d_in[12];
    const float* W_dec  = (const float*)d_in[13];
    const float* b_dec  = (const float*)d_in[14];
    float* out = (float*)d_out;

    float *p_dt, *p_bc, *p_y, *p_y2, *p_hA, *p_hB, *p_cA, *p_cH, *p_ci;
    cudaGetSymbolAddress((void**)&p_dt, g_dt);
    cudaGetSymbolAddress((void**)&p_bc, g_bc);
    cudaGetSymbolAddress((void**)&p_y,  g_y);
    cudaGetSymbolAddress((void**)&p_y2, g_y2);
    cudaGetSymbolAddress((void**)&p_hA, g_hA);
    cudaGetSymbolAddress((void**)&p_hB, g_hB);
    cudaGetSymbolAddress((void**)&p_cA, g_cA);
    cudaGetSymbolAddress((void**)&p_cH, g_cH);
    cudaGetSymbolAddress((void**)&p_ci, g_ci);

    cudaFuncSetAttribute(gemm_tc<0>, cudaFuncAttributeMaxDynamicSharedMemorySize,
                         GEMM_SMEM_BYTES);
    cudaFuncSetAttribute(gemm_tc<1>, cudaFuncAttributeMaxDynamicSharedMemorySize,
                         GEMM_SMEM_BYTES);

    const dim3 gemmGrid(DD / 64, MM / 128);       // (8, 64)
    const dim3 scanGrid(DD / 16, NCH, BB);        // (32, 16, 4)

    const float* hin = x;
    float* houts[2] = { p_hA, p_hB };

    for (int l = 0; l < NLAYERS; l++) {
        gemm_tc<1><<<gemmGrid, 256, GEMM_SMEM_BYTES>>>(
            hin, W_dt + (size_t)l * DD * DD, b_dt + l * DD, p_dt);
        bc_kernel<<<MM / 8, 256>>>(hin, W_B + (size_t)l * DD * NN, b_B + l * NN,
                                   W_C + (size_t)l * DD * NN, b_C + l * NN, p_bc);
        scan_carry<<<scanGrid, 256>>>(hin, p_dt, p_bc,
                                      A_log + (size_t)l * DD * NN, p_cA, p_cH);
        carry_combine<<<BB * DD * NN / 256, 256>>>(p_cA, p_cH, p_ci);
        scan_apply<<<scanGrid, 256>>>(hin, p_dt, p_bc,
                                      A_log + (size_t)l * DD * NN,
                                      D_skip + l * DD, p_ci, p_y);
        gemm_tc<0><<<gemmGrid, 256, GEMM_SMEM_BYTES>>>(
            p_y, W_mix + (size_t)l * DD * DD, b_mix + l * DD, p_y2);
        ln_res_kernel<<<MM, 128>>>(hin, p_y2, ln_g + l * DD, ln_b + l * DD, houts[l]);
        hin = houts[l];
    }

    gemm_tc<0><<<gemmGrid, 256, GEMM_SMEM_BYTES>>>(hin, W_dec, b_dec, out);
}

// round 4
// speedup vs baseline: 3.1451x; 1.0384x over previous
#include <cuda_runtime.h>
#include <cuda_bf16.h>
#include <cstddef>
#include <cstdint>

// Problem constants
#define NLAYERS 2
#define BB 4
#define LL 2048
#define DD 512
#define NN 16
#define OO 512
#define MM (BB * LL)   // 8192 rows

// scan chunking
#define NCH 16
#define CL (LL / NCH)  // 128

// ---------------- scratch buffers (no allocation allowed) ----------------
__device__ float g_dt[MM * DD];     // softplus(dt) per layer
__device__ float g_bc[MM * 2 * NN]; // [row][32]: 0..15 = Bm, 16..31 = Cm
__device__ float g_y[MM * DD];      // scan output (post-gelu)
__device__ float g_y2[MM * DD];     // mix GEMM output (pre-LN)
__device__ float g_hA[MM * DD];     // layer outputs
__device__ float g_hB[MM * DD];
__device__ float g_cA[BB * NCH * DD * NN];  // chunk A-product
__device__ float g_cH[BB * NCH * DD * NN];  // chunk local h_end
__device__ float g_ci[BB * NCH * DD * NN];  // chunk initial h

// ---------------- helpers ----------------
__device__ __forceinline__ float softplus_f(float v) {
    return fmaxf(v, 0.f) + log1pf(__expf(-fabsf(v)));
}

__device__ __forceinline__ float gelu_f(float v) {
    return 0.5f * v * (1.f + erff(v * 0.70710678118654752440f));
}

__device__ __forceinline__ uint32_t f2tf32(float f) {
    uint32_t u;
    asm("cvt.rna.tf32.f32 %0, %1;" : "=r"(u) : "f"(f));
    return u;
}

__device__ __forceinline__ void mma_tf32(float4& d,
                                         const uint32_t* a,
                                         uint32_t b0, uint32_t b1,
                                         const float4& c) {
    asm volatile(
        "mma.sync.aligned.m16n8k8.row.col.f32.tf32.tf32.f32 "
        "{%0,%1,%2,%3}, {%4,%5,%6,%7}, {%8,%9}, {%10,%11,%12,%13};"
        : "=f"(d.x), "=f"(d.y), "=f"(d.z), "=f"(d.w)
        : "r"(a[0]), "r"(a[1]), "r"(a[2]), "r"(a[3]),
          "r"(b0), "r"(b1),
          "f"(c.x), "f"(c.y), "f"(c.z), "f"(c.w));
}

// ---------------- tensor-core GEMM: C = A[M,512] @ W[512,512] + bias ----------------
// CTA 128x64, k-tile 32, 8 warps (4M x 2N), warp tile 32x32.
// smem holds PRE-CONVERTED tf32 bits (no cvt in compute loop).
#define AS_STRIDE 36
#define BS_STRIDE 72
#define AS_TILE (128 * AS_STRIDE)
#define BS_TILE (32 * BS_STRIDE)
#define GEMM_SMEM_BYTES ((2 * AS_TILE + 2 * BS_TILE) * 4)

template <int EPI>
__global__ void __launch_bounds__(256, 2)
gemm_tc(const float* __restrict__ A,
        const float* __restrict__ W,
        const float* __restrict__ bias,
        float* __restrict__ C) {
    extern __shared__ uint32_t smem[];
    uint32_t* As = smem;
    uint32_t* Bs = smem + 2 * AS_TILE;

    const int tid  = threadIdx.x;
    const int lane = tid & 31;
    const int warp = tid >> 5;
    const int g    = lane >> 2;
    const int tig  = lane & 3;
    const int mBase = (warp >> 1) * 32;
    const int nBase = (warp & 1) * 32;

    const int m0 = blockIdx.y * 128;
    const int n0 = blockIdx.x * 64;

    // loader mappings
    const int aRow = tid >> 3;            // 0..31 step-> with +256*i gives 0..127
    const int aKc  = (tid & 7) * 4;       // 0..28
    const int bRow = tid >> 4;            // 0..15 -> +16
    const int bNc  = (tid & 15) * 4;      // 0..60

    float4 acc[2][4];
#pragma unroll
    for (int t = 0; t < 2; t++)
#pragma unroll
        for (int j = 0; j < 4; j++) acc[t][j] = make_float4(0.f, 0.f, 0.f, 0.f);

    float4 aR[4], bR[2];

    auto ldg_tile = [&](int kt) {
#pragma unroll
        for (int i = 0; i < 4; i++) {
            int row = aRow + 32 * i;
            aR[i] = *(const float4*)(A + (size_t)(m0 + row) * 512 + kt * 32 + aKc);
        }
#pragma unroll
        for (int i = 0; i < 2; i++) {
            int row = bRow + 16 * i;
            bR[i] = *(const float4*)(W + (size_t)(kt * 32 + row) * 512 + n0 + bNc);
        }
    };

    auto sts_tile = [&](int stage) {
        uint32_t* as = As + stage * AS_TILE;
        uint32_t* bs = Bs + stage * BS_TILE;
#pragma unroll
        for (int i = 0; i < 4; i++) {
            int row = aRow + 32 * i;
            uint4 v;
            v.x = f2tf32(aR[i].x); v.y = f2tf32(aR[i].y);
            v.z = f2tf32(aR[i].z); v.w = f2tf32(aR[i].w);
            *(uint4*)(as + row * AS_STRIDE + aKc) = v;
        }
#pragma unroll
        for (int i = 0; i < 2; i++) {
            int row = bRow + 16 * i;
            uint4 v;
            v.x = f2tf32(bR[i].x); v.y = f2tf32(bR[i].y);
            v.z = f2tf32(bR[i].z); v.w = f2tf32(bR[i].w);
            *(uint4*)(bs + row * BS_STRIDE + bNc) = v;
        }
    };

    ldg_tile(0);
    sts_tile(0);
    __syncthreads();

    const int NKT = 512 / 32;  // 16
    for (int kt = 0; kt < NKT; kt++) {
        if (kt + 1 < NKT) ldg_tile(kt + 1);

        const uint32_t* as = As + (kt & 1) * AS_TILE;
        const uint32_t* bs = Bs + (kt & 1) * BS_TILE;

#pragma unroll
        for (int s = 0; s < 4; s++) {
            const int k = s * 8 + tig;
            uint32_t afr[2][4];
#pragma unroll
            for (int t = 0; t < 2; t++) {
                const int r = mBase + 16 * t + g;
                afr[t][0] = as[r * AS_STRIDE + k];
                afr[t][1] = as[(r + 8) * AS_STRIDE + k];
                afr[t][2] = as[r * AS_STRIDE + k + 4];
                afr[t][3] = as[(r + 8) * AS_STRIDE + k + 4];
            }
#pragma unroll
            for (int j = 0; j < 4; j++) {
                uint32_t b0 = bs[k * BS_STRIDE + nBase + 8 * j + g];
                uint32_t b1 = bs[(k + 4) * BS_STRIDE + nBase + 8 * j + g];
                mma_tf32(acc[0][j], afr[0], b0, b1, acc[0][j]);
                mma_tf32(acc[1][j], afr[1], b0, b1, acc[1][j]);
            }
        }

        if (kt + 1 < NKT) {
            sts_tile((kt + 1) & 1);
            __syncthreads();
        }
    }

#pragma unroll
    for (int t = 0; t < 2; t++) {
#pragma unroll
        for (int j = 0; j < 4; j++) {
            const int row = m0 + mBase + 16 * t + g;
            const int col = n0 + nBase + 8 * j + tig * 2;
            float b0 = bias[col], b1 = bias[col + 1];
            float v0 = acc[t][j].x + b0;
            float v1 = acc[t][j].y + b1;
            float v2 = acc[t][j].z + b0;
            float v3 = acc[t][j].w + b1;
            if (EPI == 1) {
                v0 = softplus_f(v0); v1 = softplus_f(v1);
                v2 = softplus_f(v2); v3 = softplus_f(v3);
            }
            *(float2*)(C + (size_t)row * 512 + col) = make_float2(v0, v1);
            *(float2*)(C + (size_t)(row + 8) * 512 + col) = make_float2(v2, v3);
        }
    }
}

// ---------------- B/C projection: [M,512] @ [512,16] x2 ----------------
__global__ void bc_kernel(const float* __restrict__ X,
                          const float* __restrict__ WB, const float* __restrict__ bB,
                          const float* __restrict__ WC, const float* __restrict__ bC,
                          float* __restrict__ BC) {
    __shared__ float xs[8][DD];
    const int tid = threadIdx.x;
    const int row0 = blockIdx.x * 8;

    for (int i = tid; i < 8 * (DD / 4); i += 256) {
        int r = i >> 7;
        int c4 = i & 127;
        ((float4*)xs[r])[c4] = ((const float4*)(X + (size_t)(row0 + r) * DD))[c4];
    }
    __syncthreads();

    const int r = tid >> 5;
    const int c = tid & 31;
    const int n = c & 15;
    const float* Wp = (c < 16) ? WB : WC;
    float acc = (c < 16) ? bB[n] : bC[n];
    const float* xr = xs[r];
#pragma unroll 8
    for (int k = 0; k < DD; k++) acc = fmaf(xr[k], __ldg(Wp + k * NN + n), acc);
    BC[(size_t)(row0 + r) * 32 + c] = acc;
}

// ---------------- scan pass 1: per-chunk carry (A_prod, h_end) ----------------
// grid = (D/16, NCH, B), block = 256 = 16 d x 16 n.  All inputs staged in smem.
__global__ void scan_carry(const float* __restrict__ X,
                           const float* __restrict__ DT,
                           const float* __restrict__ BC,
                           const float* __restrict__ A_log,
                           float* __restrict__ cA,
                           float* __restrict__ cH) {
    __shared__ float sdt[CL][16];
    __shared__ float sx[CL][16];
    __shared__ float sB[CL][16];

    const int tid = threadIdx.x;
    const int n  = tid & 15;
    const int dl = tid >> 4;
    const int d0 = blockIdx.x * 16;
    const int d  = d0 + dl;
    const int ch = blockIdx.y;
    const int b  = blockIdx.z;

    const float* Xb  = X  + (size_t)b * LL * DD + (size_t)ch * CL * DD;
    const float* DTb = DT + (size_t)b * LL * DD + (size_t)ch * CL * DD;
    const float* BCb = BC + (size_t)b * LL * 32 + (size_t)ch * CL * 32;

    // stage: dt/x tiles (CL x 16) and B tile (CL x 16) via float4
#pragma unroll
    for (int i = 0; i < 2; i++) {
        int idx = tid + 256 * i;          // 0..511
        int l = idx >> 2;
        int q = (idx & 3) * 4;
        *(float4*)&sdt[l][q] = *(const float4*)(DTb + (size_t)l * DD + d0 + q);
        *(float4*)&sx[l][q]  = *(const float4*)(Xb  + (size_t)l * DD + d0 + q);
        *(float4*)&sB[l][q]  = *(const float4*)(BCb + l * 32 + q);
    }
    __syncthreads();

    const float Acoef = -__expf(A_log[d * NN + n]);
    float h = 0.f, Ap = 1.f;

#pragma unroll 4
    for (int l = 0; l < CL; l++) {
        const float dtv = sdt[l][dl];
        const float xv  = sx[l][dl];
        const float Bv  = sB[l][n];
        const float a = __expf(dtv * Acoef);
        h = fmaf(a, h, dtv * xv * Bv);
        Ap *= a;
    }
    const size_t o = ((size_t)(b * NCH + ch) * DD + d) * NN + n;
    cA[o] = Ap;
    cH[o] = h;
}

// ---------------- scan pass 2: sequential combine over chunks ----------------
__global__ void carry_combine(const float* __restrict__ cA,
                              const float* __restrict__ cH,
                              float* __restrict__ ci) {
    const int t = blockIdx.x * 256 + threadIdx.x;   // 0..32767
    const int b = t >> 13;
    const int r = t & 8191;
    float h = 0.f;
#pragma unroll
    for (int c = 0; c < NCH; c++) {
        const size_t o = (size_t)(b * NCH + c) * (DD * NN) + r;
        ci[o] = h;
        h = fmaf(cA[o], h, cH[o]);
    }
}

// ---------------- scan pass 3: per-chunk scan + C-contract + skip + GELU ------
__global__ void scan_apply(const float* __restrict__ X,
                           const float* __restrict__ DT,
                           const float* __restrict__ BC,
                           const float* __restrict__ A_log,
                           const float* __restrict__ Dskip,
                           const float* __restrict__ ci,
                           float* __restrict__ Y) {
    __shared__ float sdt[CL][16];
    __shared__ float sx[CL][16];
    __shared__ float sB[CL][16];
    __shared__ float sC[CL][16];
    __shared__ float sY[CL][16];

    const int tid = threadIdx.x;
    const int n  = tid & 15;
    const int dl = tid >> 4;
    const int d0 = blockIdx.x * 16;
    const int d  = d0 + dl;
    const int ch = blockIdx.y;
    const int b  = blockIdx.z;

    const float* Xb  = X  + (size_t)b * LL * DD + (size_t)ch * CL * DD;
    const float* DTb = DT + (size_t)b * LL * DD + (size_t)ch * CL * DD;
    const float* BCb = BC + (size_t)b * LL * 32 + (size_t)ch * CL * 32;
    float*       Yb  = Y  + (size_t)b * LL * DD + (size_t)ch * CL * DD;

#pragma unroll
    for (int i = 0; i < 2; i++) {
        int idx = tid + 256 * i;          // 0..511
        int l = idx >> 2;
        int q = (idx & 3) * 4;
        *(float4*)&sdt[l][q] = *(const float4*)(DTb + (size_t)l * DD + d0 + q);
        *(float4*)&sx[l][q]  = *(const float4*)(Xb  + (size_t)l * DD + d0 + q);
        *(float4*)&sB[l][q]  = *(const float4*)(BCb + l * 32 + q);
        *(float4*)&sC[l][q]  = *(const float4*)(BCb + l * 32 + 16 + q);
    }
    __syncthreads();

    const float Acoef = -__expf(A_log[d * NN + n]);
    const float dsk = Dskip[d];
    float h = ci[((size_t)(b * NCH + ch) * DD + d) * NN + n];

    for (int l0 = 0; l0 < CL; l0 += 4) {
        float p[4], xc[4];
#pragma unroll
        for (int u = 0; u < 4; u++) {
            const int l = l0 + u;
            const float dtv = sdt[l][dl];
            xc[u] = sx[l][dl];
            const float Bv = sB[l][n];
            const float a = __expf(dtv * Acoef);
            h = fmaf(a, h, dtv * xc[u] * Bv);
            p[u] = sC[l][n] * h;
        }
#pragma unroll
        for (int u = 0; u < 4; u++) p[u] += __shfl_xor_sync(0xffffffffu, p[u], 8, 16);
#pragma unroll
        for (int u = 0; u < 4; u++) p[u] += __shfl_xor_sync(0xffffffffu, p[u], 4, 16);
#pragma unroll
        for (int u = 0; u < 4; u++) p[u] += __shfl_xor_sync(0xffffffffu, p[u], 2, 16);
#pragma unroll
        for (int u = 0; u < 4; u++) p[u] += __shfl_xor_sync(0xffffffffu, p[u], 1, 16);

        if (n == 0) {
#pragma unroll
            for (int u = 0; u < 4; u++)
                sY[l0 + u][dl] = gelu_f(fmaf(dsk, xc[u], p[u]));
        }
    }
    __syncthreads();

    // cooperative coalesced writeback
#pragma unroll
    for (int i = 0; i < 2; i++) {
        int idx = tid + 256 * i;
        int l = idx >> 2;
        int q = (idx & 3) * 4;
        *(float4*)(Yb + (size_t)l * DD + d0 + q) = *(float4*)&sY[l][q];
    }
}

// ---------------- layernorm + residual ----------------
__global__ void ln_res_kernel(const float* __restrict__ Hin,
                              const float* __restrict__ Y2,
                              const float* __restrict__ g,
                              const float* __restrict__ bb,
                              float* __restrict__ Hout) {
    __shared__ float red[4];
    const int row = blockIdx.x;
    const int tid = threadIdx.x;
    const float* yr = Y2 + (size_t)row * DD;

    float v[4];
    float s = 0.f;
#pragma unroll
    for (int j = 0; j < 4; j++) { v[j] = yr[tid + j * 128]; s += v[j]; }

#pragma unroll
    for (int o = 16; o > 0; o >>= 1) s += __shfl_xor_sync(0xffffffffu, s, o);
    if ((tid & 31) == 0) red[tid >> 5] = s;
    __syncthreads();
    const float mean = (red[0] + red[1] + red[2] + red[3]) * (1.f / DD);
    __syncthreads();

    float sq = 0.f;
#pragma unroll
    for (int j = 0; j < 4; j++) { float dlt = v[j] - mean; sq += dlt * dlt; }
#pragma unroll
    for (int o = 16; o > 0; o >>= 1) sq += __shfl_xor_sync(0xffffffffu, sq, o);
    if ((tid & 31) == 0) red[tid >> 5] = sq;
    __syncthreads();
    const float var = (red[0] + red[1] + red[2] + red[3]) * (1.f / DD);
    const float rstd = rsqrtf(var + 1e-5f);

#pragma unroll
    for (int j = 0; j < 4; j++) {
        const int col = tid + j * 128;
        float o = (v[j] - mean) * rstd * g[col] + bb[col];
        Hout[(size_t)row * DD + col] = Hin[(size_t)row * DD + col] + o;
    }
}

// ---------------- launch ----------------
extern "C" void kernel_launch(void* const* d_in, const int* in_sizes, int n_in,
                              void* d_out, int out_size) {
    const float* x      = (const float*)d_in[0];
    const float* A_log  = (const float*)d_in[1];
    const float* W_B    = (const float*)d_in[2];
    const float* b_B    = (const float*)d_in[3];
    const float* W_C    = (const float*)d_in[4];
    const float* b_C    = (const float*)d_in[5];
    const float* W_dt   = (const float*)d_in[6];
    const float* b_dt   = (const float*)d_in[7];
    const float* D_skip = (const float*)d_in[8];
    const float* W_mix  = (const float*)d_in[9];
    const float* b_mix  = (const float*)d_in[10];
    const float* ln_g   = (const float*)d_in[11];
    const float* ln_b   = (const float*)d_in[12];
    const float* W_dec  = (const float*)d_in[13];
    const float* b_dec  = (const float*)d_in[14];
    float* out = (float*)d_out;

    float *p_dt, *p_bc, *p_y, *p_y2, *p_hA, *p_hB, *p_cA, *p_cH, *p_ci;
    cudaGetSymbolAddress((void**)&p_dt, g_dt);
    cudaGetSymbolAddress((void**)&p_bc, g_bc);
    cudaGetSymbolAddress((void**)&p_y,  g_y);
    cudaGetSymbolAddress((void**)&p_y2, g_y2);
    cudaGetSymbolAddress((void**)&p_hA, g_hA);
    cudaGetSymbolAddress((void**)&p_hB, g_hB);
    cudaGetSymbolAddress((void**)&p_cA, g_cA);
    cudaGetSymbolAddress((void**)&p_cH, g_cH);
    cudaGetSymbolAddress((void**)&p_ci, g_ci);

    cudaFuncSetAttribute(gemm_tc<0>, cudaFuncAttributeMaxDynamicSharedMemorySize,
                         GEMM_SMEM_BYTES);
    cudaFuncSetAttribute(gemm_tc<1>, cudaFuncAttributeMaxDynamicSharedMemorySize,
                         GEMM_SMEM_BYTES);

    const dim3 gemmGrid(DD / 64, MM / 128);       // (8, 64)
    const dim3 scanGrid(DD / 16, NCH, BB);        // (32, 16, 4)

    const float* hin = x;
    float* houts[2] = { p_hA, p_hB };

    for (int l = 0; l < NLAYERS; l++) {
        gemm_tc<1><<<gemmGrid, 256, GEMM_SMEM_BYTES>>>(
            hin, W_dt + (size_t)l * DD * DD, b_dt + l * DD, p_dt);
        bc_kernel<<<MM / 8, 256>>>(hin, W_B + (size_t)l * DD * NN, b_B + l * NN,
                                   W_C + (size_t)l * DD * NN, b_C + l * NN, p_bc);
        scan_carry<<<scanGrid, 256>>>(hin, p_dt, p_bc,
                                      A_log + (size_t)l * DD * NN, p_cA, p_cH);
        carry_combine<<<BB * DD * NN / 256, 256>>>(p_cA, p_cH, p_ci);
        scan_apply<<<scanGrid, 256>>>(hin, p_dt, p_bc,
                                      A_log + (size_t)l * DD * NN,
                                      D_skip + l * DD, p_ci, p_y);
        gemm_tc<0><<<gemmGrid, 256, GEMM_SMEM_BYTES>>>(
            p_y, W_mix + (size_t)l * DD * DD, b_mix + l * DD, p_y2);
        ln_res_kernel<<<MM, 128>>>(hin, p_y2, ln_g + l * DD, ln_b + l * DD, houts[l]);
        hin = houts[l];
    }

    gemm_tc<0><<<gemmGrid, 256, GEMM_SMEM_BYTES>>>(hin, W_dec, b_dec, out);
}

// round 5
// speedup vs baseline: 3.4429x; 1.0947x over previous
#include <cuda_runtime.h>
#include <cuda_bf16.h>
#include <cstddef>
#include <cstdint>

// Problem constants
#define NLAYERS 2
#define BB 4
#define LL 2048
#define DD 512
#define NN 16
#define OO 512
#define MM (BB * LL)   // 8192 rows

// scan chunking
#define NCH 16
#define CL (LL / NCH)  // 128

// ---------------- scratch buffers (no allocation allowed) ----------------
__device__ float g_dt[MM * DD];     // softplus(dt) per layer
__device__ float g_bc[MM * 2 * NN]; // [row][32]: 0..15 = Bm, 16..31 = Cm
__device__ float g_y[MM * DD];      // scan output (post-gelu)
__device__ float g_y2[MM * DD];     // mix GEMM output (pre-LN)
__device__ float g_hA[MM * DD];     // layer outputs
__device__ float g_hB[MM * DD];
__device__ float g_cA[BB * NCH * DD * NN];  // chunk A-product
__device__ float g_cH[BB * NCH * DD * NN];  // chunk local h_end

// ---------------- helpers ----------------
__device__ __forceinline__ float softplus_f(float v) {
    return fmaxf(v, 0.f) + log1pf(__expf(-fabsf(v)));
}

__device__ __forceinline__ float gelu_f(float v) {
    return 0.5f * v * (1.f + erff(v * 0.70710678118654752440f));
}

__device__ __forceinline__ uint32_t f2tf32(float f) {
    uint32_t u;
    asm("cvt.rna.tf32.f32 %0, %1;" : "=r"(u) : "f"(f));
    return u;
}

__device__ __forceinline__ void mma_tf32(float4& d,
                                         const uint32_t* a,
                                         uint32_t b0, uint32_t b1,
                                         const float4& c) {
    asm volatile(
        "mma.sync.aligned.m16n8k8.row.col.f32.tf32.tf32.f32 "
        "{%0,%1,%2,%3}, {%4,%5,%6,%7}, {%8,%9}, {%10,%11,%12,%13};"
        : "=f"(d.x), "=f"(d.y), "=f"(d.z), "=f"(d.w)
        : "r"(a[0]), "r"(a[1]), "r"(a[2]), "r"(a[3]),
          "r"(b0), "r"(b1),
          "f"(c.x), "f"(c.y), "f"(c.z), "f"(c.w));
}

// ---------------- tensor-core GEMM: C = A[M,512] @ W[512,512] + bias ----------------
#define AS_STRIDE 36
#define BS_STRIDE 72
#define AS_TILE (128 * AS_STRIDE)
#define BS_TILE (32 * BS_STRIDE)
#define GEMM_SMEM_BYTES ((2 * AS_TILE + 2 * BS_TILE) * 4)

template <int EPI>
__global__ void __launch_bounds__(256, 2)
gemm_tc(const float* __restrict__ A,
        const float* __restrict__ W,
        const float* __restrict__ bias,
        float* __restrict__ C) {
    extern __shared__ uint32_t smem[];
    uint32_t* As = smem;
    uint32_t* Bs = smem + 2 * AS_TILE;

    const int tid  = threadIdx.x;
    const int lane = tid & 31;
    const int warp = tid >> 5;
    const int g    = lane >> 2;
    const int tig  = lane & 3;
    const int mBase = (warp >> 1) * 32;
    const int nBase = (warp & 1) * 32;

    const int m0 = blockIdx.y * 128;
    const int n0 = blockIdx.x * 64;

    const int aRow = tid >> 3;
    const int aKc  = (tid & 7) * 4;
    const int bRow = tid >> 4;
    const int bNc  = (tid & 15) * 4;

    float4 acc[2][4];
#pragma unroll
    for (int t = 0; t < 2; t++)
#pragma unroll
        for (int j = 0; j < 4; j++) acc[t][j] = make_float4(0.f, 0.f, 0.f, 0.f);

    float4 aR[4], bR[2];

    auto ldg_tile = [&](int kt) {
#pragma unroll
        for (int i = 0; i < 4; i++) {
            int row = aRow + 32 * i;
            aR[i] = *(const float4*)(A + (size_t)(m0 + row) * 512 + kt * 32 + aKc);
        }
#pragma unroll
        for (int i = 0; i < 2; i++) {
            int row = bRow + 16 * i;
            bR[i] = *(const float4*)(W + (size_t)(kt * 32 + row) * 512 + n0 + bNc);
        }
    };

    auto sts_tile = [&](int stage) {
        uint32_t* as = As + stage * AS_TILE;
        uint32_t* bs = Bs + stage * BS_TILE;
#pragma unroll
        for (int i = 0; i < 4; i++) {
            int row = aRow + 32 * i;
            uint4 v;
            v.x = f2tf32(aR[i].x); v.y = f2tf32(aR[i].y);
            v.z = f2tf32(aR[i].z); v.w = f2tf32(aR[i].w);
            *(uint4*)(as + row * AS_STRIDE + aKc) = v;
        }
#pragma unroll
        for (int i = 0; i < 2; i++) {
            int row = bRow + 16 * i;
            uint4 v;
            v.x = f2tf32(bR[i].x); v.y = f2tf32(bR[i].y);
            v.z = f2tf32(bR[i].z); v.w = f2tf32(bR[i].w);
            *(uint4*)(bs + row * BS_STRIDE + bNc) = v;
        }
    };

    ldg_tile(0);
    sts_tile(0);
    __syncthreads();

    const int NKT = 512 / 32;
    for (int kt = 0; kt < NKT; kt++) {
        if (kt + 1 < NKT) ldg_tile(kt + 1);

        const uint32_t* as = As + (kt & 1) * AS_TILE;
        const uint32_t* bs = Bs + (kt & 1) * BS_TILE;

#pragma unroll
        for (int s = 0; s < 4; s++) {
            const int k = s * 8 + tig;
            uint32_t afr[2][4];
#pragma unroll
            for (int t = 0; t < 2; t++) {
                const int r = mBase + 16 * t + g;
                afr[t][0] = as[r * AS_STRIDE + k];
                afr[t][1] = as[(r + 8) * AS_STRIDE + k];
                afr[t][2] = as[r * AS_STRIDE + k + 4];
                afr[t][3] = as[(r + 8) * AS_STRIDE + k + 4];
            }
#pragma unroll
            for (int j = 0; j < 4; j++) {
                uint32_t b0 = bs[k * BS_STRIDE + nBase + 8 * j + g];
                uint32_t b1 = bs[(k + 4) * BS_STRIDE + nBase + 8 * j + g];
                mma_tf32(acc[0][j], afr[0], b0, b1, acc[0][j]);
                mma_tf32(acc[1][j], afr[1], b0, b1, acc[1][j]);
            }
        }

        if (kt + 1 < NKT) {
            sts_tile((kt + 1) & 1);
            __syncthreads();
        }
    }

#pragma unroll
    for (int t = 0; t < 2; t++) {
#pragma unroll
        for (int j = 0; j < 4; j++) {
            const int row = m0 + mBase + 16 * t + g;
            const int col = n0 + nBase + 8 * j + tig * 2;
            float b0 = bias[col], b1 = bias[col + 1];
            float v0 = acc[t][j].x + b0;
            float v1 = acc[t][j].y + b1;
            float v2 = acc[t][j].z + b0;
            float v3 = acc[t][j].w + b1;
            if (EPI == 1) {
                v0 = softplus_f(v0); v1 = softplus_f(v1);
                v2 = softplus_f(v2); v3 = softplus_f(v3);
            }
            *(float2*)(C + (size_t)row * 512 + col) = make_float2(v0, v1);
            *(float2*)(C + (size_t)(row + 8) * 512 + col) = make_float2(v2, v3);
        }
    }
}

// ---------------- B/C projection v2: [M,512] @ [512,16] x2 ----------------
// 32 rows per block staged in smem; each thread computes 4 rows x 1 col,
// reusing each weight load 4x. block = 256 (32 cols x 8 groups).
#define BC_SMEM_BYTES (32 * DD * 4)
__global__ void bc_kernel(const float* __restrict__ X,
                          const float* __restrict__ WB, const float* __restrict__ bB,
                          const float* __restrict__ WC, const float* __restrict__ bC,
                          float* __restrict__ BC) {
    extern __shared__ float xs[];   // [32][512]
    const int tid = threadIdx.x;
    const int row0 = blockIdx.x * 32;

    for (int i = tid; i < 32 * (DD / 4); i += 256) {
        int r = i >> 7;
        int c4 = i & 127;
        ((float4*)(xs + r * DD))[c4] =
            ((const float4*)(X + (size_t)(row0 + r) * DD))[c4];
    }
    __syncthreads();

    const int c = tid & 31;
    const int grp = tid >> 5;           // 0..7 -> rows grp*4..grp*4+3
    const int n = c & 15;
    const float* Wp = (c < 16) ? WB : WC;
    const float bias = (c < 16) ? bB[n] : bC[n];

    float acc0 = bias, acc1 = bias, acc2 = bias, acc3 = bias;
    const float* x0 = xs + (grp * 4 + 0) * DD;
    const float* x1 = xs + (grp * 4 + 1) * DD;
    const float* x2 = xs + (grp * 4 + 2) * DD;
    const float* x3 = xs + (grp * 4 + 3) * DD;

#pragma unroll 4
    for (int k0 = 0; k0 < DD; k0 += 4) {
        const float w0 = __ldg(Wp + (k0 + 0) * NN + n);
        const float w1 = __ldg(Wp + (k0 + 1) * NN + n);
        const float w2 = __ldg(Wp + (k0 + 2) * NN + n);
        const float w3 = __ldg(Wp + (k0 + 3) * NN + n);
        float4 v;
        v = *(const float4*)(x0 + k0);
        acc0 = fmaf(v.x, w0, acc0); acc0 = fmaf(v.y, w1, acc0);
        acc0 = fmaf(v.z, w2, acc0); acc0 = fmaf(v.w, w3, acc0);
        v = *(const float4*)(x1 + k0);
        acc1 = fmaf(v.x, w0, acc1); acc1 = fmaf(v.y, w1, acc1);
        acc1 = fmaf(v.z, w2, acc1); acc1 = fmaf(v.w, w3, acc1);
        v = *(const float4*)(x2 + k0);
        acc2 = fmaf(v.x, w0, acc2); acc2 = fmaf(v.y, w1, acc2);
        acc2 = fmaf(v.z, w2, acc2); acc2 = fmaf(v.w, w3, acc2);
        v = *(const float4*)(x3 + k0);
        acc3 = fmaf(v.x, w0, acc3); acc3 = fmaf(v.y, w1, acc3);
        acc3 = fmaf(v.z, w2, acc3); acc3 = fmaf(v.w, w3, acc3);
    }
    BC[(size_t)(row0 + grp * 4 + 0) * 32 + c] = acc0;
    BC[(size_t)(row0 + grp * 4 + 1) * 32 + c] = acc1;
    BC[(size_t)(row0 + grp * 4 + 2) * 32 + c] = acc2;
    BC[(size_t)(row0 + grp * 4 + 3) * 32 + c] = acc3;
}

// ---------------- scan pass 1: per-chunk carry (A_prod, h_end) ----------------
__global__ void scan_carry(const float* __restrict__ X,
                           const float* __restrict__ DT,
                           const float* __restrict__ BC,
                           const float* __restrict__ A_log,
                           float* __restrict__ cA,
                           float* __restrict__ cH) {
    __shared__ float sdt[CL][16];
    __shared__ float sx[CL][16];
    __shared__ float sB[CL][16];

    const int tid = threadIdx.x;
    const int n  = tid & 15;
    const int dl = tid >> 4;
    const int d0 = blockIdx.x * 16;
    const int d  = d0 + dl;
    const int ch = blockIdx.y;
    const int b  = blockIdx.z;

    const float* Xb  = X  + (size_t)b * LL * DD + (size_t)ch * CL * DD;
    const float* DTb = DT + (size_t)b * LL * DD + (size_t)ch * CL * DD;
    const float* BCb = BC + (size_t)b * LL * 32 + (size_t)ch * CL * 32;

#pragma unroll
    for (int i = 0; i < 2; i++) {
        int idx = tid + 256 * i;
        int l = idx >> 2;
        int q = (idx & 3) * 4;
        *(float4*)&sdt[l][q] = *(const float4*)(DTb + (size_t)l * DD + d0 + q);
        *(float4*)&sx[l][q]  = *(const float4*)(Xb  + (size_t)l * DD + d0 + q);
        *(float4*)&sB[l][q]  = *(const float4*)(BCb + l * 32 + q);
    }
    __syncthreads();

    const float Acoef = -__expf(A_log[d * NN + n]);
    float h = 0.f, Ap = 1.f;

#pragma unroll 4
    for (int l = 0; l < CL; l++) {
        const float dtv = sdt[l][dl];
        const float xv  = sx[l][dl];
        const float Bv  = sB[l][n];
        const float a = __expf(dtv * Acoef);
        h = fmaf(a, h, dtv * xv * Bv);
        Ap *= a;
    }
    const size_t o = ((size_t)(b * NCH + ch) * DD + d) * NN + n;
    cA[o] = Ap;
    cH[o] = h;
}

// ---------------- scan pass 2: per-chunk scan + C-contract (carry-combine fused,
//                  GELU + D-skip deferred to writeback) ----------------
__global__ void scan_apply(const float* __restrict__ X,
                           const float* __restrict__ DT,
                           const float* __restrict__ BC,
                           const float* __restrict__ A_log,
                           const float* __restrict__ Dskip,
                           const float* __restrict__ cA,
                           const float* __restrict__ cH,
                           float* __restrict__ Y) {
    __shared__ float sdt[CL][16];
    __shared__ float sx[CL][16];
    __shared__ float sB[CL][16];
    __shared__ float sC[CL][16];
    __shared__ float sY[CL][16];
    __shared__ float sDsk[16];

    const int tid = threadIdx.x;
    const int n  = tid & 15;
    const int dl = tid >> 4;
    const int d0 = blockIdx.x * 16;
    const int d  = d0 + dl;
    const int ch = blockIdx.y;
    const int b  = blockIdx.z;

    const float* Xb  = X  + (size_t)b * LL * DD + (size_t)ch * CL * DD;
    const float* DTb = DT + (size_t)b * LL * DD + (size_t)ch * CL * DD;
    const float* BCb = BC + (size_t)b * LL * 32 + (size_t)ch * CL * 32;
    float*       Yb  = Y  + (size_t)b * LL * DD + (size_t)ch * CL * DD;

#pragma unroll
    for (int i = 0; i < 2; i++) {
        int idx = tid + 256 * i;
        int l = idx >> 2;
        int q = (idx & 3) * 4;
        *(float4*)&sdt[l][q] = *(const float4*)(DTb + (size_t)l * DD + d0 + q);
        *(float4*)&sx[l][q]  = *(const float4*)(Xb  + (size_t)l * DD + d0 + q);
        *(float4*)&sB[l][q]  = *(const float4*)(BCb + l * 32 + q);
        *(float4*)&sC[l][q]  = *(const float4*)(BCb + l * 32 + 16 + q);
    }
    if (tid < 16) sDsk[tid] = Dskip[d0 + tid];

    // initial h for this chunk: sequential combine over preceding chunk carries
    float h = 0.f;
    const size_t base = ((size_t)b * NCH * DD + d) * NN + n;
    for (int c = 0; c < ch; c++) {
        const size_t o = base + (size_t)c * (DD * NN);
        h = fmaf(cA[o], h, cH[o]);
    }

    const float Acoef = -__expf(A_log[d * NN + n]);
    __syncthreads();

    for (int l0 = 0; l0 < CL; l0 += 4) {
        float p[4];
#pragma unroll
        for (int u = 0; u < 4; u++) {
            const int l = l0 + u;
            const float dtv = sdt[l][dl];
            const float Bv = sB[l][n];
            const float a = __expf(dtv * Acoef);
            h = fmaf(a, h, dtv * sx[l][dl] * Bv);
            p[u] = sC[l][n] * h;
        }
#pragma unroll
        for (int u = 0; u < 4; u++) p[u] += __shfl_xor_sync(0xffffffffu, p[u], 8, 16);
#pragma unroll
        for (int u = 0; u < 4; u++) p[u] += __shfl_xor_sync(0xffffffffu, p[u], 4, 16);
#pragma unroll
        for (int u = 0; u < 4; u++) p[u] += __shfl_xor_sync(0xffffffffu, p[u], 2, 16);
#pragma unroll
        for (int u = 0; u < 4; u++) p[u] += __shfl_xor_sync(0xffffffffu, p[u], 1, 16);

        if (n == 0) {
#pragma unroll
            for (int u = 0; u < 4; u++) sY[l0 + u][dl] = p[u];
        }
    }
    __syncthreads();

    // cooperative writeback with deferred D-skip + GELU
#pragma unroll
    for (int i = 0; i < 2; i++) {
        int idx = tid + 256 * i;
        int l = idx >> 2;
        int q = (idx & 3) * 4;
        float4 o;
        o.x = gelu_f(fmaf(sDsk[q + 0], sx[l][q + 0], sY[l][q + 0]));
        o.y = gelu_f(fmaf(sDsk[q + 1], sx[l][q + 1], sY[l][q + 1]));
        o.z = gelu_f(fmaf(sDsk[q + 2], sx[l][q + 2], sY[l][q + 2]));
        o.w = gelu_f(fmaf(sDsk[q + 3], sx[l][q + 3], sY[l][q + 3]));
        *(float4*)(Yb + (size_t)l * DD + d0 + q) = o;
    }
}

// ---------------- layernorm + residual ----------------
__global__ void ln_res_kernel(const float* __restrict__ Hin,
                              const float* __restrict__ Y2,
                              const float* __restrict__ g,
                              const float* __restrict__ bb,
                              float* __restrict__ Hout) {
    __shared__ float red[4];
    const int row = blockIdx.x;
    const int tid = threadIdx.x;
    const float* yr = Y2 + (size_t)row * DD;

    float v[4];
    float s = 0.f;
#pragma unroll
    for (int j = 0; j < 4; j++) { v[j] = yr[tid + j * 128]; s += v[j]; }

#pragma unroll
    for (int o = 16; o > 0; o >>= 1) s += __shfl_xor_sync(0xffffffffu, s, o);
    if ((tid & 31) == 0) red[tid >> 5] = s;
    __syncthreads();
    const float mean = (red[0] + red[1] + red[2] + red[3]) * (1.f / DD);
    __syncthreads();

    float sq = 0.f;
#pragma unroll
    for (int j = 0; j < 4; j++) { float dlt = v[j] - mean; sq += dlt * dlt; }
#pragma unroll
    for (int o = 16; o > 0; o >>= 1) sq += __shfl_xor_sync(0xffffffffu, sq, o);
    if ((tid & 31) == 0) red[tid >> 5] = sq;
    __syncthreads();
    const float var = (red[0] + red[1] + red[2] + red[3]) * (1.f / DD);
    const float rstd = rsqrtf(var + 1e-5f);

#pragma unroll
    for (int j = 0; j < 4; j++) {
        const int col = tid + j * 128;
        float o = (v[j] - mean) * rstd * g[col] + bb[col];
        Hout[(size_t)row * DD + col] = Hin[(size_t)row * DD + col] + o;
    }
}

// ---------------- launch ----------------
extern "C" void kernel_launch(void* const* d_in, const int* in_sizes, int n_in,
                              void* d_out, int out_size) {
    const float* x      = (const float*)d_in[0];
    const float* A_log  = (const float*)d_in[1];
    const float* W_B    = (const float*)d_in[2];
    const float* b_B    = (const float*)d_in[3];
    const float* W_C    = (const float*)d_in[4];
    const float* b_C    = (const float*)d_in[5];
    const float* W_dt   = (const float*)d_in[6];
    const float* b_dt   = (const float*)d_in[7];
    const float* D_skip = (const float*)d_in[8];
    const float* W_mix  = (const float*)d_in[9];
    const float* b_mix  = (const float*)d_in[10];
    const float* ln_g   = (const float*)d_in[11];
    const float* ln_b   = (const float*)d_in[12];
    const float* W_dec  = (const float*)d_in[13];
    const float* b_dec  = (const float*)d_in[14];
    float* out = (float*)d_out;

    float *p_dt, *p_bc, *p_y, *p_y2, *p_hA, *p_hB, *p_cA, *p_cH;
    cudaGetSymbolAddress((void**)&p_dt, g_dt);
    cudaGetSymbolAddress((void**)&p_bc, g_bc);
    cudaGetSymbolAddress((void**)&p_y,  g_y);
    cudaGetSymbolAddress((void**)&p_y2, g_y2);
    cudaGetSymbolAddress((void**)&p_hA, g_hA);
    cudaGetSymbolAddress((void**)&p_hB, g_hB);
    cudaGetSymbolAddress((void**)&p_cA, g_cA);
    cudaGetSymbolAddress((void**)&p_cH, g_cH);

    cudaFuncSetAttribute(gemm_tc<0>, cudaFuncAttributeMaxDynamicSharedMemorySize,
                         GEMM_SMEM_BYTES);
    cudaFuncSetAttribute(gemm_tc<1>, cudaFuncAttributeMaxDynamicSharedMemorySize,
                         GEMM_SMEM_BYTES);
    cudaFuncSetAttribute(bc_kernel, cudaFuncAttributeMaxDynamicSharedMemorySize,
                         BC_SMEM_BYTES);

    const dim3 gemmGrid(DD / 64, MM / 128);       // (8, 64)
    const dim3 scanGrid(DD / 16, NCH, BB);        // (32, 16, 4)

    const float* hin = x;
    float* houts[2] = { p_hA, p_hB };

    for (int l = 0; l < NLAYERS; l++) {
        gemm_tc<1><<<gemmGrid, 256, GEMM_SMEM_BYTES>>>(
            hin, W_dt + (size_t)l * DD * DD, b_dt + l * DD, p_dt);
        bc_kernel<<<MM / 32, 256, BC_SMEM_BYTES>>>(
            hin, W_B + (size_t)l * DD * NN, b_B + l * NN,
            W_C + (size_t)l * DD * NN, b_C + l * NN, p_bc);
        scan_carry<<<scanGrid, 256>>>(hin, p_dt, p_bc,
                                      A_log + (size_t)l * DD * NN, p_cA, p_cH);
        scan_apply<<<scanGrid, 256>>>(hin, p_dt, p_bc,
                                      A_log + (size_t)l * DD * NN,
                                      D_skip + l * DD, p_cA, p_cH, p_y);
        gemm_tc<0><<<gemmGrid, 256, GEMM_SMEM_BYTES>>>(
            p_y, W_mix + (size_t)l * DD * DD, b_mix + l * DD, p_y2);
        ln_res_kernel<<<MM, 128>>>(hin, p_y2, ln_g + l * DD, ln_b + l * DD, houts[l]);
        hin = houts[l];
    }

    gemm_tc<0><<<gemmGrid, 256, GEMM_SMEM_BYTES>>>(hin, W_dec, b_dec, out);
}

// round 6
// speedup vs baseline: 3.9921x; 1.1595x over previous
#include <cuda_runtime.h>
#include <cuda_bf16.h>
#include <cstddef>
#include <cstdint>

// Problem constants
#define NLAYERS 2
#define BB 4
#define LL 2048
#define DD 512
#define NN 16
#define OO 512
#define MM (BB * LL)   // 8192 rows

// scan chunking
#define NCH 16
#define CL (LL / NCH)  // 128
#define SC_D 32        // d-columns per scan block

// ---------------- scratch buffers (no allocation allowed) ----------------
__device__ float g_dt[MM * DD];     // softplus(dt) per layer
__device__ float g_bc[MM * 2 * NN]; // [row][32]: 0..15 = Bm, 16..31 = Cm
__device__ float g_y[MM * DD];      // scan output (post-gelu)
__device__ float g_y2[MM * DD];     // mix GEMM output (pre-LN)
__device__ float g_hA[MM * DD];     // layer outputs
__device__ float g_hB[MM * DD];
__device__ float g_cA[BB * NCH * DD * NN];  // chunk A-product
__device__ float g_cH[BB * NCH * DD * NN];  // chunk local h_end

// ---------------- helpers ----------------
__device__ __forceinline__ float softplus_f(float v) {
    return fmaxf(v, 0.f) + log1pf(__expf(-fabsf(v)));
}

__device__ __forceinline__ float gelu_f(float v) {
    return 0.5f * v * (1.f + erff(v * 0.70710678118654752440f));
}

__device__ __forceinline__ float ex2f(float x) {
    float y;
    asm("ex2.approx.f32 %0, %1;" : "=f"(y) : "f"(x));
    return y;
}

#define LOG2E 1.4426950408889634f

__device__ __forceinline__ uint32_t f2tf32(float f) {
    uint32_t u;
    asm("cvt.rna.tf32.f32 %0, %1;" : "=r"(u) : "f"(f));
    return u;
}

__device__ __forceinline__ void mma_tf32(float4& d,
                                         const uint32_t* a,
                                         uint32_t b0, uint32_t b1,
                                         const float4& c) {
    asm volatile(
        "mma.sync.aligned.m16n8k8.row.col.f32.tf32.tf32.f32 "
        "{%0,%1,%2,%3}, {%4,%5,%6,%7}, {%8,%9}, {%10,%11,%12,%13};"
        : "=f"(d.x), "=f"(d.y), "=f"(d.z), "=f"(d.w)
        : "r"(a[0]), "r"(a[1]), "r"(a[2]), "r"(a[3]),
          "r"(b0), "r"(b1),
          "f"(c.x), "f"(c.y), "f"(c.z), "f"(c.w));
}

// ---------------- tensor-core GEMM: C = A[M,512] @ W[512,512] + bias ----------------
#define AS_STRIDE 36
#define BS_STRIDE 72
#define AS_TILE (128 * AS_STRIDE)
#define BS_TILE (32 * BS_STRIDE)
#define GEMM_SMEM_BYTES ((2 * AS_TILE + 2 * BS_TILE) * 4)

template <int EPI>
__global__ void __launch_bounds__(256, 2)
gemm_tc(const float* __restrict__ A,
        const float* __restrict__ W,
        const float* __restrict__ bias,
        float* __restrict__ C) {
    extern __shared__ uint32_t smem[];
    uint32_t* As = smem;
    uint32_t* Bs = smem + 2 * AS_TILE;

    const int tid  = threadIdx.x;
    const int lane = tid & 31;
    const int warp = tid >> 5;
    const int g    = lane >> 2;
    const int tig  = lane & 3;
    const int mBase = (warp >> 1) * 32;
    const int nBase = (warp & 1) * 32;

    const int m0 = blockIdx.y * 128;
    const int n0 = blockIdx.x * 64;

    const int aRow = tid >> 3;
    const int aKc  = (tid & 7) * 4;
    const int bRow = tid >> 4;
    const int bNc  = (tid & 15) * 4;

    float4 acc[2][4];
#pragma unroll
    for (int t = 0; t < 2; t++)
#pragma unroll
        for (int j = 0; j < 4; j++) acc[t][j] = make_float4(0.f, 0.f, 0.f, 0.f);

    float4 aR[4], bR[2];

    auto ldg_tile = [&](int kt) {
#pragma unroll
        for (int i = 0; i < 4; i++) {
            int row = aRow + 32 * i;
            aR[i] = *(const float4*)(A + (size_t)(m0 + row) * 512 + kt * 32 + aKc);
        }
#pragma unroll
        for (int i = 0; i < 2; i++) {
            int row = bRow + 16 * i;
            bR[i] = *(const float4*)(W + (size_t)(kt * 32 + row) * 512 + n0 + bNc);
        }
    };

    auto sts_tile = [&](int stage) {
        uint32_t* as = As + stage * AS_TILE;
        uint32_t* bs = Bs + stage * BS_TILE;
#pragma unroll
        for (int i = 0; i < 4; i++) {
            int row = aRow + 32 * i;
            uint4 v;
            v.x = f2tf32(aR[i].x); v.y = f2tf32(aR[i].y);
            v.z = f2tf32(aR[i].z); v.w = f2tf32(aR[i].w);
            *(uint4*)(as + row * AS_STRIDE + aKc) = v;
        }
#pragma unroll
        for (int i = 0; i < 2; i++) {
            int row = bRow + 16 * i;
            uint4 v;
            v.x = f2tf32(bR[i].x); v.y = f2tf32(bR[i].y);
            v.z = f2tf32(bR[i].z); v.w = f2tf32(bR[i].w);
            *(uint4*)(bs + row * BS_STRIDE + bNc) = v;
        }
    };

    ldg_tile(0);
    sts_tile(0);
    __syncthreads();

    const int NKT = 512 / 32;
    for (int kt = 0; kt < NKT; kt++) {
        if (kt + 1 < NKT) ldg_tile(kt + 1);

        const uint32_t* as = As + (kt & 1) * AS_TILE;
        const uint32_t* bs = Bs + (kt & 1) * BS_TILE;

#pragma unroll
        for (int s = 0; s < 4; s++) {
            const int k = s * 8 + tig;
            uint32_t afr[2][4];
#pragma unroll
            for (int t = 0; t < 2; t++) {
                const int r = mBase + 16 * t + g;
                afr[t][0] = as[r * AS_STRIDE + k];
                afr[t][1] = as[(r + 8) * AS_STRIDE + k];
                afr[t][2] = as[r * AS_STRIDE + k + 4];
                afr[t][3] = as[(r + 8) * AS_STRIDE + k + 4];
            }
#pragma unroll
            for (int j = 0; j < 4; j++) {
                uint32_t b0 = bs[k * BS_STRIDE + nBase + 8 * j + g];
                uint32_t b1 = bs[(k + 4) * BS_STRIDE + nBase + 8 * j + g];
                mma_tf32(acc[0][j], afr[0], b0, b1, acc[0][j]);
                mma_tf32(acc[1][j], afr[1], b0, b1, acc[1][j]);
            }
        }

        if (kt + 1 < NKT) {
            sts_tile((kt + 1) & 1);
            __syncthreads();
        }
    }

#pragma unroll
    for (int t = 0; t < 2; t++) {
#pragma unroll
        for (int j = 0; j < 4; j++) {
            const int row = m0 + mBase + 16 * t + g;
            const int col = n0 + nBase + 8 * j + tig * 2;
            float b0 = bias[col], b1 = bias[col + 1];
            float v0 = acc[t][j].x + b0;
            float v1 = acc[t][j].y + b1;
            float v2 = acc[t][j].z + b0;
            float v3 = acc[t][j].w + b1;
            if (EPI == 1) {
                v0 = softplus_f(v0); v1 = softplus_f(v1);
                v2 = softplus_f(v2); v3 = softplus_f(v3);
            }
            *(float2*)(C + (size_t)row * 512 + col) = make_float2(v0, v1);
            *(float2*)(C + (size_t)(row + 8) * 512 + col) = make_float2(v2, v3);
        }
    }
}

// ---------------- B/C projection v2: [M,512] @ [512,16] x2 ----------------
#define BC_SMEM_BYTES (32 * DD * 4)
__global__ void bc_kernel(const float* __restrict__ X,
                          const float* __restrict__ WB, const float* __restrict__ bB,
                          const float* __restrict__ WC, const float* __restrict__ bC,
                          float* __restrict__ BC) {
    extern __shared__ float xs[];   // [32][512]
    const int tid = threadIdx.x;
    const int row0 = blockIdx.x * 32;

    for (int i = tid; i < 32 * (DD / 4); i += 256) {
        int r = i >> 7;
        int c4 = i & 127;
        ((float4*)(xs + r * DD))[c4] =
            ((const float4*)(X + (size_t)(row0 + r) * DD))[c4];
    }
    __syncthreads();

    const int c = tid & 31;
    const int grp = tid >> 5;
    const int n = c & 15;
    const float* Wp = (c < 16) ? WB : WC;
    const float bias = (c < 16) ? bB[n] : bC[n];

    float acc0 = bias, acc1 = bias, acc2 = bias, acc3 = bias;
    const float* x0 = xs + (grp * 4 + 0) * DD;
    const float* x1 = xs + (grp * 4 + 1) * DD;
    const float* x2 = xs + (grp * 4 + 2) * DD;
    const float* x3 = xs + (grp * 4 + 3) * DD;

#pragma unroll 4
    for (int k0 = 0; k0 < DD; k0 += 4) {
        const float w0 = __ldg(Wp + (k0 + 0) * NN + n);
        const float w1 = __ldg(Wp + (k0 + 1) * NN + n);
        const float w2 = __ldg(Wp + (k0 + 2) * NN + n);
        const float w3 = __ldg(Wp + (k0 + 3) * NN + n);
        float4 v;
        v = *(const float4*)(x0 + k0);
        acc0 = fmaf(v.x, w0, acc0); acc0 = fmaf(v.y, w1, acc0);
        acc0 = fmaf(v.z, w2, acc0); acc0 = fmaf(v.w, w3, acc0);
        v = *(const float4*)(x1 + k0);
        acc1 = fmaf(v.x, w0, acc1); acc1 = fmaf(v.y, w1, acc1);
        acc1 = fmaf(v.z, w2, acc1); acc1 = fmaf(v.w, w3, acc1);
        v = *(const float4*)(x2 + k0);
        acc2 = fmaf(v.x, w0, acc2); acc2 = fmaf(v.y, w1, acc2);
        acc2 = fmaf(v.z, w2, acc2); acc2 = fmaf(v.w, w3, acc2);
        v = *(const float4*)(x3 + k0);
        acc3 = fmaf(v.x, w0, acc3); acc3 = fmaf(v.y, w1, acc3);
        acc3 = fmaf(v.z, w2, acc3); acc3 = fmaf(v.w, w3, acc3);
    }
    BC[(size_t)(row0 + grp * 4 + 0) * 32 + c] = acc0;
    BC[(size_t)(row0 + grp * 4 + 1) * 32 + c] = acc1;
    BC[(size_t)(row0 + grp * 4 + 2) * 32 + c] = acc2;
    BC[(size_t)(row0 + grp * 4 + 3) * 32 + c] = acc3;
}

// ---------------- scan pass 1: per-chunk carry (A_prod, h_end) ----------------
// block = 128 = 32 d x 4 n-groups; each thread owns 4 n-states in registers.
// grid = (D/32, NCH, B)
__global__ void __launch_bounds__(128)
scan_carry(const float* __restrict__ X,
           const float* __restrict__ DT,
           const float* __restrict__ BC,
           const float* __restrict__ A_log,
           float* __restrict__ cA,
           float* __restrict__ cH) {
    __shared__ float sdt[CL][SC_D];
    __shared__ float sx[CL][SC_D];
    __shared__ float sB[CL][16];

    const int tid = threadIdx.x;
    const int dl = tid >> 2;          // 0..31
    const int n0 = (tid & 3) * 4;     // 0,4,8,12
    const int d0 = blockIdx.x * SC_D;
    const int d  = d0 + dl;
    const int ch = blockIdx.y;
    const int b  = blockIdx.z;

    const float* Xb  = X  + (size_t)b * LL * DD + (size_t)ch * CL * DD;
    const float* DTb = DT + (size_t)b * LL * DD + (size_t)ch * CL * DD;
    const float* BCb = BC + (size_t)b * LL * 32 + (size_t)ch * CL * 32;

#pragma unroll
    for (int i = 0; i < 8; i++) {
        int idx = tid + 128 * i;          // 0..1023
        int l = idx >> 3;
        int q = (idx & 7) * 4;
        *(float4*)&sdt[l][q] = *(const float4*)(DTb + (size_t)l * DD + d0 + q);
        *(float4*)&sx[l][q]  = *(const float4*)(Xb  + (size_t)l * DD + d0 + q);
    }
#pragma unroll
    for (int i = 0; i < 4; i++) {
        int idx = tid + 128 * i;          // 0..511
        int l = idx >> 2;
        int q = (idx & 3) * 4;
        *(float4*)&sB[l][q] = *(const float4*)(BCb + l * 32 + q);
    }
    __syncthreads();

    float Ac2[4];
#pragma unroll
    for (int j = 0; j < 4; j++)
        Ac2[j] = -__expf(A_log[d * NN + n0 + j]) * LOG2E;

    float h[4] = {0.f, 0.f, 0.f, 0.f};
    float Ap[4] = {1.f, 1.f, 1.f, 1.f};

#pragma unroll 4
    for (int l = 0; l < CL; l++) {
        const float dtv = sdt[l][dl];
        const float dtx = dtv * sx[l][dl];
        const float4 B4 = *(const float4*)&sB[l][n0];
        float a0 = ex2f(dtv * Ac2[0]);
        float a1 = ex2f(dtv * Ac2[1]);
        float a2 = ex2f(dtv * Ac2[2]);
        float a3 = ex2f(dtv * Ac2[3]);
        h[0] = fmaf(a0, h[0], dtx * B4.x); Ap[0] *= a0;
        h[1] = fmaf(a1, h[1], dtx * B4.y); Ap[1] *= a1;
        h[2] = fmaf(a2, h[2], dtx * B4.z); Ap[2] *= a2;
        h[3] = fmaf(a3, h[3], dtx * B4.w); Ap[3] *= a3;
    }
    const size_t o = ((size_t)(b * NCH + ch) * DD + d) * NN + n0;
    *(float4*)(cA + o) = make_float4(Ap[0], Ap[1], Ap[2], Ap[3]);
    *(float4*)(cH + o) = make_float4(h[0], h[1], h[2], h[3]);
}

// ---------------- scan pass 2: per-chunk scan + C-contract ----------------
// Same thread layout; carry-combine fused; GELU + D-skip deferred to writeback.
// dynamic smem: sdt[CL][32] sx[CL][32] sB[CL][16] sC[CL][16] sY[CL][32]
#define SCAN_SMEM_BYTES ((CL * SC_D * 3 + CL * 16 * 2) * 4)
__global__ void __launch_bounds__(128)
scan_apply(const float* __restrict__ X,
           const float* __restrict__ DT,
           const float* __restrict__ BC,
           const float* __restrict__ A_log,
           const float* __restrict__ Dskip,
           const float* __restrict__ cA,
           const float* __restrict__ cH,
           float* __restrict__ Y) {
    extern __shared__ float ssm[];
    float* sdt = ssm;                          // CL*32
    float* sx  = sdt + CL * SC_D;              // CL*32
    float* sB  = sx + CL * SC_D;               // CL*16
    float* sC  = sB + CL * 16;                 // CL*16
    float* sY  = sC + CL * 16;                 // CL*32

    const int tid = threadIdx.x;
    const int dl = tid >> 2;
    const int n0 = (tid & 3) * 4;
    const int d0 = blockIdx.x * SC_D;
    const int d  = d0 + dl;
    const int ch = blockIdx.y;
    const int b  = blockIdx.z;

    const float* Xb  = X  + (size_t)b * LL * DD + (size_t)ch * CL * DD;
    const float* DTb = DT + (size_t)b * LL * DD + (size_t)ch * CL * DD;
    const float* BCb = BC + (size_t)b * LL * 32 + (size_t)ch * CL * 32;
    float*       Yb  = Y  + (size_t)b * LL * DD + (size_t)ch * CL * DD;

#pragma unroll
    for (int i = 0; i < 8; i++) {
        int idx = tid + 128 * i;
        int l = idx >> 3;
        int q = (idx & 7) * 4;
        *(float4*)(sdt + l * SC_D + q) = *(const float4*)(DTb + (size_t)l * DD + d0 + q);
        *(float4*)(sx + l * SC_D + q)  = *(const float4*)(Xb  + (size_t)l * DD + d0 + q);
    }
#pragma unroll
    for (int i = 0; i < 4; i++) {
        int idx = tid + 128 * i;
        int l = idx >> 2;
        int q = (idx & 3) * 4;
        *(float4*)(sB + l * 16 + q) = *(const float4*)(BCb + l * 32 + q);
        *(float4*)(sC + l * 16 + q) = *(const float4*)(BCb + l * 32 + 16 + q);
    }

    // initial h: sequential combine over preceding chunk carries (float4)
    float h[4] = {0.f, 0.f, 0.f, 0.f};
    {
        const size_t base = ((size_t)b * NCH * DD + d) * NN + n0;
        for (int c = 0; c < ch; c++) {
            const size_t o = base + (size_t)c * (DD * NN);
            const float4 A4 = *(const float4*)(cA + o);
            const float4 H4 = *(const float4*)(cH + o);
            h[0] = fmaf(A4.x, h[0], H4.x);
            h[1] = fmaf(A4.y, h[1], H4.y);
            h[2] = fmaf(A4.z, h[2], H4.z);
            h[3] = fmaf(A4.w, h[3], H4.w);
        }
    }

    float Ac2[4];
#pragma unroll
    for (int j = 0; j < 4; j++)
        Ac2[j] = -__expf(A_log[d * NN + n0 + j]) * LOG2E;

    __syncthreads();

#pragma unroll 4
    for (int l = 0; l < CL; l++) {
        const float dtv = sdt[l * SC_D + dl];
        const float dtx = dtv * sx[l * SC_D + dl];
        const float4 B4 = *(const float4*)(sB + l * 16 + n0);
        const float4 C4 = *(const float4*)(sC + l * 16 + n0);
        float a0 = ex2f(dtv * Ac2[0]);
        float a1 = ex2f(dtv * Ac2[1]);
        float a2 = ex2f(dtv * Ac2[2]);
        float a3 = ex2f(dtv * Ac2[3]);
        h[0] = fmaf(a0, h[0], dtx * B4.x);
        h[1] = fmaf(a1, h[1], dtx * B4.y);
        h[2] = fmaf(a2, h[2], dtx * B4.z);
        h[3] = fmaf(a3, h[3], dtx * B4.w);
        float p01 = fmaf(C4.y, h[1], C4.x * h[0]);
        float p23 = fmaf(C4.w, h[3], C4.z * h[2]);
        float p = p01 + p23;
        p += __shfl_xor_sync(0xffffffffu, p, 1, 4);
        p += __shfl_xor_sync(0xffffffffu, p, 2, 4);
        if (n0 == 0) sY[l * SC_D + dl] = p;
    }
    __syncthreads();

    // cooperative writeback with deferred D-skip + GELU
#pragma unroll
    for (int i = 0; i < 8; i++) {
        int idx = tid + 128 * i;
        int l = idx >> 3;
        int q = (idx & 7) * 4;
        const float4 dk = *(const float4*)(Dskip + d0 + q);
        const float4 xv = *(const float4*)(sx + l * SC_D + q);
        const float4 pv = *(const float4*)(sY + l * SC_D + q);
        float4 o;
        o.x = gelu_f(fmaf(dk.x, xv.x, pv.x));
        o.y = gelu_f(fmaf(dk.y, xv.y, pv.y));
        o.z = gelu_f(fmaf(dk.z, xv.z, pv.z));
        o.w = gelu_f(fmaf(dk.w, xv.w, pv.w));
        *(float4*)(Yb + (size_t)l * DD + d0 + q) = o;
    }
}

// ---------------- layernorm + residual ----------------
__global__ void ln_res_kernel(const float* __restrict__ Hin,
                              const float* __restrict__ Y2,
                              const float* __restrict__ g,
                              const float* __restrict__ bb,
                              float* __restrict__ Hout) {
    __shared__ float red[4];
    const int row = blockIdx.x;
    const int tid = threadIdx.x;
    const float* yr = Y2 + (size_t)row * DD;

    float v[4];
    float s = 0.f;
#pragma unroll
    for (int j = 0; j < 4; j++) { v[j] = yr[tid + j * 128]; s += v[j]; }

#pragma unroll
    for (int o = 16; o > 0; o >>= 1) s += __shfl_xor_sync(0xffffffffu, s, o);
    if ((tid & 31) == 0) red[tid >> 5] = s;
    __syncthreads();
    const float mean = (red[0] + red[1] + red[2] + red[3]) * (1.f / DD);
    __syncthreads();

    float sq = 0.f;
#pragma unroll
    for (int j = 0; j < 4; j++) { float dlt = v[j] - mean; sq += dlt * dlt; }
#pragma unroll
    for (int o = 16; o > 0; o >>= 1) sq += __shfl_xor_sync(0xffffffffu, sq, o);
    if ((tid & 31) == 0) red[tid >> 5] = sq;
    __syncthreads();
    const float var = (red[0] + red[1] + red[2] + red[3]) * (1.f / DD);
    const float rstd = rsqrtf(var + 1e-5f);

#pragma unroll
    for (int j = 0; j < 4; j++) {
        const int col = tid + j * 128;
        float o = (v[j] - mean) * rstd * g[col] + bb[col];
        Hout[(size_t)row * DD + col] = Hin[(size_t)row * DD + col] + o;
    }
}

// ---------------- launch ----------------
extern "C" void kernel_launch(void* const* d_in, const int* in_sizes, int n_in,
                              void* d_out, int out_size) {
    const float* x      = (const float*)d_in[0];
    const float* A_log  = (const float*)d_in[1];
    const float* W_B    = (const float*)d_in[2];
    const float* b_B    = (const float*)d_in[3];
    const float* W_C    = (const float*)d_in[4];
    const float* b_C    = (const float*)d_in[5];
    const float* W_dt   = (const float*)d_in[6];
    const float* b_dt   = (const float*)d_in[7];
    const float* D_skip = (const float*)d_in[8];
    const float* W_mix  = (const float*)d_in[9];
    const float* b_mix  = (const float*)d_in[10];
    const float* ln_g   = (const float*)d_in[11];
    const float* ln_b   = (const float*)d_in[12];
    const float* W_dec  = (const float*)d_in[13];
    const float* b_dec  = (const float*)d_in[14];
    float* out = (float*)d_out;

    float *p_dt, *p_bc, *p_y, *p_y2, *p_hA, *p_hB, *p_cA, *p_cH;
    cudaGetSymbolAddress((void**)&p_dt, g_dt);
    cudaGetSymbolAddress((void**)&p_bc, g_bc);
    cudaGetSymbolAddress((void**)&p_y,  g_y);
    cudaGetSymbolAddress((void**)&p_y2, g_y2);
    cudaGetSymbolAddress((void**)&p_hA, g_hA);
    cudaGetSymbolAddress((void**)&p_hB, g_hB);
    cudaGetSymbolAddress((void**)&p_cA, g_cA);
    cudaGetSymbolAddress((void**)&p_cH, g_cH);

    cudaFuncSetAttribute(gemm_tc<0>, cudaFuncAttributeMaxDynamicSharedMemorySize,
                         GEMM_SMEM_BYTES);
    cudaFuncSetAttribute(gemm_tc<1>, cudaFuncAttributeMaxDynamicSharedMemorySize,
                         GEMM_SMEM_BYTES);
    cudaFuncSetAttribute(bc_kernel, cudaFuncAttributeMaxDynamicSharedMemorySize,
                         BC_SMEM_BYTES);
    cudaFuncSetAttribute(scan_apply, cudaFuncAttributeMaxDynamicSharedMemorySize,
                         SCAN_SMEM_BYTES);

    const dim3 gemmGrid(DD / 64, MM / 128);       // (8, 64)
    const dim3 scanGrid(DD / SC_D, NCH, BB);      // (16, 16, 4)

    const float* hin = x;
    float* houts[2] = { p_hA, p_hB };

    for (int l = 0; l < NLAYERS; l++) {
        gemm_tc<1><<<gemmGrid, 256, GEMM_SMEM_BYTES>>>(
            hin, W_dt + (size_t)l * DD * DD, b_dt + l * DD, p_dt);
        bc_kernel<<<MM / 32, 256, BC_SMEM_BYTES>>>(
            hin, W_B + (size_t)l * DD * NN, b_B + l * NN,
            W_C + (size_t)l * DD * NN, b_C + l * NN, p_bc);
        scan_carry<<<scanGrid, 128>>>(hin, p_dt, p_bc,
                                      A_log + (size_t)l * DD * NN, p_cA, p_cH);
        scan_apply<<<scanGrid, 128, SCAN_SMEM_BYTES>>>(
            hin, p_dt, p_bc, A_log + (size_t)l * DD * NN,
            D_skip + l * DD, p_cA, p_cH, p_y);
        gemm_tc<0><<<gemmGrid, 256, GEMM_SMEM_BYTES>>>(
            p_y, W_mix + (size_t)l * DD * DD, b_mix + l * DD, p_y2);
        ln_res_kernel<<<MM, 128>>>(hin, p_y2, ln_g + l * DD, ln_b + l * DD, houts[l]);
        hin = houts[l];
    }

    gemm_tc<0><<<gemmGrid, 256, GEMM_SMEM_BYTES>>>(hin, W_dec, b_dec, out);
}

// round 7
// speedup vs baseline: 4.1094x; 1.0294x over previous
#include <cuda_runtime.h>
#include <cuda_bf16.h>
#include <cstddef>
#include <cstdint>

// Problem constants
#define NLAYERS 2
#define BB 4
#define LL 2048
#define DD 512
#define NN 16
#define OO 512
#define MM (BB * LL)   // 8192 rows

// scan chunking
#define NCH 32
#define CL (LL / NCH)  // 64
#define SC_D 32        // d-columns per scan block

// ---------------- scratch buffers (no allocation allowed) ----------------
__device__ float g_dt[MM * DD];     // softplus(dt) per layer
__device__ float g_bc[MM * 2 * NN]; // [row][32]: 0..15 = Bm, 16..31 = Cm
__device__ float g_y[MM * DD];      // scan output (post-gelu)
__device__ float g_y2[MM * DD];     // mix GEMM output (pre-LN)
__device__ float g_hA[MM * DD];     // layer outputs
__device__ float g_hB[MM * DD];
__device__ float g_cA[BB * NCH * DD * NN];  // chunk A-product
__device__ float g_cH[BB * NCH * DD * NN];  // chunk local h_end

// ---------------- helpers ----------------
__device__ __forceinline__ float softplus_f(float v) {
    return fmaxf(v, 0.f) + log1pf(__expf(-fabsf(v)));
}

__device__ __forceinline__ float gelu_f(float v) {
    return 0.5f * v * (1.f + erff(v * 0.70710678118654752440f));
}

__device__ __forceinline__ float ex2f(float x) {
    float y;
    asm("ex2.approx.f32 %0, %1;" : "=f"(y) : "f"(x));
    return y;
}

#define LOG2E 1.4426950408889634f

__device__ __forceinline__ uint32_t f2tf32(float f) {
    uint32_t u;
    asm("cvt.rna.tf32.f32 %0, %1;" : "=r"(u) : "f"(f));
    return u;
}

__device__ __forceinline__ void mma_tf32(float4& d,
                                         const uint32_t* a,
                                         uint32_t b0, uint32_t b1,
                                         const float4& c) {
    asm volatile(
        "mma.sync.aligned.m16n8k8.row.col.f32.tf32.tf32.f32 "
        "{%0,%1,%2,%3}, {%4,%5,%6,%7}, {%8,%9}, {%10,%11,%12,%13};"
        : "=f"(d.x), "=f"(d.y), "=f"(d.z), "=f"(d.w)
        : "r"(a[0]), "r"(a[1]), "r"(a[2]), "r"(a[3]),
          "r"(b0), "r"(b1),
          "f"(c.x), "f"(c.y), "f"(c.z), "f"(c.w));
}

// ---------------- tensor-core GEMM: C = A[M,512] @ W[512,512] + bias ----------------
#define AS_STRIDE 36
#define BS_STRIDE 72
#define AS_TILE (128 * AS_STRIDE)
#define BS_TILE (32 * BS_STRIDE)
#define GEMM_SMEM_BYTES ((2 * AS_TILE + 2 * BS_TILE) * 4)

template <int EPI>
__global__ void __launch_bounds__(256, 2)
gemm_tc(const float* __restrict__ A,
        const float* __restrict__ W,
        const float* __restrict__ bias,
        float* __restrict__ C) {
    extern __shared__ uint32_t smem[];
    uint32_t* As = smem;
    uint32_t* Bs = smem + 2 * AS_TILE;

    const int tid  = threadIdx.x;
    const int lane = tid & 31;
    const int warp = tid >> 5;
    const int g    = lane >> 2;
    const int tig  = lane & 3;
    const int mBase = (warp >> 1) * 32;
    const int nBase = (warp & 1) * 32;

    const int m0 = blockIdx.y * 128;
    const int n0 = blockIdx.x * 64;

    const int aRow = tid >> 3;
    const int aKc  = (tid & 7) * 4;
    const int bRow = tid >> 4;
    const int bNc  = (tid & 15) * 4;

    float4 acc[2][4];
#pragma unroll
    for (int t = 0; t < 2; t++)
#pragma unroll
        for (int j = 0; j < 4; j++) acc[t][j] = make_float4(0.f, 0.f, 0.f, 0.f);

    float4 aR[4], bR[2];

    auto ldg_tile = [&](int kt) {
#pragma unroll
        for (int i = 0; i < 4; i++) {
            int row = aRow + 32 * i;
            aR[i] = *(const float4*)(A + (size_t)(m0 + row) * 512 + kt * 32 + aKc);
        }
#pragma unroll
        for (int i = 0; i < 2; i++) {
            int row = bRow + 16 * i;
            bR[i] = *(const float4*)(W + (size_t)(kt * 32 + row) * 512 + n0 + bNc);
        }
    };

    auto sts_tile = [&](int stage) {
        uint32_t* as = As + stage * AS_TILE;
        uint32_t* bs = Bs + stage * BS_TILE;
#pragma unroll
        for (int i = 0; i < 4; i++) {
            int row = aRow + 32 * i;
            uint4 v;
            v.x = f2tf32(aR[i].x); v.y = f2tf32(aR[i].y);
            v.z = f2tf32(aR[i].z); v.w = f2tf32(aR[i].w);
            *(uint4*)(as + row * AS_STRIDE + aKc) = v;
        }
#pragma unroll
        for (int i = 0; i < 2; i++) {
            int row = bRow + 16 * i;
            uint4 v;
            v.x = f2tf32(bR[i].x); v.y = f2tf32(bR[i].y);
            v.z = f2tf32(bR[i].z); v.w = f2tf32(bR[i].w);
            *(uint4*)(bs + row * BS_STRIDE + bNc) = v;
        }
    };

    ldg_tile(0);
    sts_tile(0);
    __syncthreads();

    const int NKT = 512 / 32;
    for (int kt = 0; kt < NKT; kt++) {
        if (kt + 1 < NKT) ldg_tile(kt + 1);

        const uint32_t* as = As + (kt & 1) * AS_TILE;
        const uint32_t* bs = Bs + (kt & 1) * BS_TILE;

#pragma unroll
        for (int s = 0; s < 4; s++) {
            const int k = s * 8 + tig;
            uint32_t afr[2][4];
#pragma unroll
            for (int t = 0; t < 2; t++) {
                const int r = mBase + 16 * t + g;
                afr[t][0] = as[r * AS_STRIDE + k];
                afr[t][1] = as[(r + 8) * AS_STRIDE + k];
                afr[t][2] = as[r * AS_STRIDE + k + 4];
                afr[t][3] = as[(r + 8) * AS_STRIDE + k + 4];
            }
#pragma unroll
            for (int j = 0; j < 4; j++) {
                uint32_t b0 = bs[k * BS_STRIDE + nBase + 8 * j + g];
                uint32_t b1 = bs[(k + 4) * BS_STRIDE + nBase + 8 * j + g];
                mma_tf32(acc[0][j], afr[0], b0, b1, acc[0][j]);
                mma_tf32(acc[1][j], afr[1], b0, b1, acc[1][j]);
            }
        }

        if (kt + 1 < NKT) {
            sts_tile((kt + 1) & 1);
            __syncthreads();
        }
    }

#pragma unroll
    for (int t = 0; t < 2; t++) {
#pragma unroll
        for (int j = 0; j < 4; j++) {
            const int row = m0 + mBase + 16 * t + g;
            const int col = n0 + nBase + 8 * j + tig * 2;
            float b0 = bias[col], b1 = bias[col + 1];
            float v0 = acc[t][j].x + b0;
            float v1 = acc[t][j].y + b1;
            float v2 = acc[t][j].z + b0;
            float v3 = acc[t][j].w + b1;
            if (EPI == 1) {
                v0 = softplus_f(v0); v1 = softplus_f(v1);
                v2 = softplus_f(v2); v3 = softplus_f(v3);
            }
            *(float2*)(C + (size_t)row * 512 + col) = make_float2(v0, v1);
            *(float2*)(C + (size_t)(row + 8) * 512 + col) = make_float2(v2, v3);
        }
    }
}

// ---------------- B/C projection v2: [M,512] @ [512,16] x2 ----------------
#define BC_SMEM_BYTES (32 * DD * 4)
__global__ void bc_kernel(const float* __restrict__ X,
                          const float* __restrict__ WB, const float* __restrict__ bB,
                          const float* __restrict__ WC, const float* __restrict__ bC,
                          float* __restrict__ BC) {
    extern __shared__ float xs[];   // [32][512]
    const int tid = threadIdx.x;
    const int row0 = blockIdx.x * 32;

    for (int i = tid; i < 32 * (DD / 4); i += 256) {
        int r = i >> 7;
        int c4 = i & 127;
        ((float4*)(xs + r * DD))[c4] =
            ((const float4*)(X + (size_t)(row0 + r) * DD))[c4];
    }
    __syncthreads();

    const int c = tid & 31;
    const int grp = tid >> 5;
    const int n = c & 15;
    const float* Wp = (c < 16) ? WB : WC;
    const float bias = (c < 16) ? bB[n] : bC[n];

    float acc0 = bias, acc1 = bias, acc2 = bias, acc3 = bias;
    const float* x0 = xs + (grp * 4 + 0) * DD;
    const float* x1 = xs + (grp * 4 + 1) * DD;
    const float* x2 = xs + (grp * 4 + 2) * DD;
    const float* x3 = xs + (grp * 4 + 3) * DD;

#pragma unroll 4
    for (int k0 = 0; k0 < DD; k0 += 4) {
        const float w0 = __ldg(Wp + (k0 + 0) * NN + n);
        const float w1 = __ldg(Wp + (k0 + 1) * NN + n);
        const float w2 = __ldg(Wp + (k0 + 2) * NN + n);
        const float w3 = __ldg(Wp + (k0 + 3) * NN + n);
        float4 v;
        v = *(const float4*)(x0 + k0);
        acc0 = fmaf(v.x, w0, acc0); acc0 = fmaf(v.y, w1, acc0);
        acc0 = fmaf(v.z, w2, acc0); acc0 = fmaf(v.w, w3, acc0);
        v = *(const float4*)(x1 + k0);
        acc1 = fmaf(v.x, w0, acc1); acc1 = fmaf(v.y, w1, acc1);
        acc1 = fmaf(v.z, w2, acc1); acc1 = fmaf(v.w, w3, acc1);
        v = *(const float4*)(x2 + k0);
        acc2 = fmaf(v.x, w0, acc2); acc2 = fmaf(v.y, w1, acc2);
        acc2 = fmaf(v.z, w2, acc2); acc2 = fmaf(v.w, w3, acc2);
        v = *(const float4*)(x3 + k0);
        acc3 = fmaf(v.x, w0, acc3); acc3 = fmaf(v.y, w1, acc3);
        acc3 = fmaf(v.z, w2, acc3); acc3 = fmaf(v.w, w3, acc3);
    }
    BC[(size_t)(row0 + grp * 4 + 0) * 32 + c] = acc0;
    BC[(size_t)(row0 + grp * 4 + 1) * 32 + c] = acc1;
    BC[(size_t)(row0 + grp * 4 + 2) * 32 + c] = acc2;
    BC[(size_t)(row0 + grp * 4 + 3) * 32 + c] = acc3;
}

// ---------------- scan pass 1: per-chunk carry (A_prod, h_end) ----------------
// block = 128 = 32 d x 4 n-groups; each thread owns 4 n-states in registers.
// grid = (D/32, NCH, B)
__global__ void __launch_bounds__(128)
scan_carry(const float* __restrict__ X,
           const float* __restrict__ DT,
           const float* __restrict__ BC,
           const float* __restrict__ A_log,
           float* __restrict__ cA,
           float* __restrict__ cH) {
    __shared__ float sdt[CL][SC_D];
    __shared__ float sx[CL][SC_D];
    __shared__ float sB[CL][16];

    const int tid = threadIdx.x;
    const int dl = tid >> 2;          // 0..31
    const int n0 = (tid & 3) * 4;     // 0,4,8,12
    const int d0 = blockIdx.x * SC_D;
    const int d  = d0 + dl;
    const int ch = blockIdx.y;
    const int b  = blockIdx.z;

    const float* Xb  = X  + (size_t)b * LL * DD + (size_t)ch * CL * DD;
    const float* DTb = DT + (size_t)b * LL * DD + (size_t)ch * CL * DD;
    const float* BCb = BC + (size_t)b * LL * 32 + (size_t)ch * CL * 32;

#pragma unroll
    for (int i = 0; i < 4; i++) {
        int idx = tid + 128 * i;          // 0..511
        int l = idx >> 3;
        int q = (idx & 7) * 4;
        *(float4*)&sdt[l][q] = *(const float4*)(DTb + (size_t)l * DD + d0 + q);
        *(float4*)&sx[l][q]  = *(const float4*)(Xb  + (size_t)l * DD + d0 + q);
    }
#pragma unroll
    for (int i = 0; i < 2; i++) {
        int idx = tid + 128 * i;          // 0..255
        int l = idx >> 2;
        int q = (idx & 3) * 4;
        *(float4*)&sB[l][q] = *(const float4*)(BCb + l * 32 + q);
    }
    __syncthreads();

    float Ac2[4];
#pragma unroll
    for (int j = 0; j < 4; j++)
        Ac2[j] = -__expf(A_log[d * NN + n0 + j]) * LOG2E;

    float h[4] = {0.f, 0.f, 0.f, 0.f};
    float Ap[4] = {1.f, 1.f, 1.f, 1.f};

#pragma unroll 4
    for (int l = 0; l < CL; l++) {
        const float dtv = sdt[l][dl];
        const float dtx = dtv * sx[l][dl];
        const float4 B4 = *(const float4*)&sB[l][n0];
        float a0 = ex2f(dtv * Ac2[0]);
        float a1 = ex2f(dtv * Ac2[1]);
        float a2 = ex2f(dtv * Ac2[2]);
        float a3 = ex2f(dtv * Ac2[3]);
        h[0] = fmaf(a0, h[0], dtx * B4.x); Ap[0] *= a0;
        h[1] = fmaf(a1, h[1], dtx * B4.y); Ap[1] *= a1;
        h[2] = fmaf(a2, h[2], dtx * B4.z); Ap[2] *= a2;
        h[3] = fmaf(a3, h[3], dtx * B4.w); Ap[3] *= a3;
    }
    const size_t o = ((size_t)(b * NCH + ch) * DD + d) * NN + n0;
    *(float4*)(cA + o) = make_float4(Ap[0], Ap[1], Ap[2], Ap[3]);
    *(float4*)(cH + o) = make_float4(h[0], h[1], h[2], h[3]);
}

// ---------------- scan pass 2: per-chunk scan + C-contract ----------------
// dynamic smem: sdt[CL][32] sx[CL][32] sB[CL][16] sC[CL][16] sY[CL][32]
#define SCAN_SMEM_BYTES ((CL * SC_D * 3 + CL * 16 * 2) * 4)
__global__ void __launch_bounds__(128)
scan_apply(const float* __restrict__ X,
           const float* __restrict__ DT,
           const float* __restrict__ BC,
           const float* __restrict__ A_log,
           const float* __restrict__ Dskip,
           const float* __restrict__ cA,
           const float* __restrict__ cH,
           float* __restrict__ Y) {
    extern __shared__ float ssm[];
    float* sdt = ssm;                          // CL*32
    float* sx  = sdt + CL * SC_D;              // CL*32
    float* sB  = sx + CL * SC_D;               // CL*16
    float* sC  = sB + CL * 16;                 // CL*16
    float* sY  = sC + CL * 16;                 // CL*32

    const int tid = threadIdx.x;
    const int dl = tid >> 2;
    const int n0 = (tid & 3) * 4;
    const int d0 = blockIdx.x * SC_D;
    const int d  = d0 + dl;
    const int ch = blockIdx.y;
    const int b  = blockIdx.z;

    const float* Xb  = X  + (size_t)b * LL * DD + (size_t)ch * CL * DD;
    const float* DTb = DT + (size_t)b * LL * DD + (size_t)ch * CL * DD;
    const float* BCb = BC + (size_t)b * LL * 32 + (size_t)ch * CL * 32;
    float*       Yb  = Y  + (size_t)b * LL * DD + (size_t)ch * CL * DD;

#pragma unroll
    for (int i = 0; i < 4; i++) {
        int idx = tid + 128 * i;
        int l = idx >> 3;
        int q = (idx & 7) * 4;
        *(float4*)(sdt + l * SC_D + q) = *(const float4*)(DTb + (size_t)l * DD + d0 + q);
        *(float4*)(sx + l * SC_D + q)  = *(const float4*)(Xb  + (size_t)l * DD + d0 + q);
    }
#pragma unroll
    for (int i = 0; i < 2; i++) {
        int idx = tid + 128 * i;
        int l = idx >> 2;
        int q = (idx & 3) * 4;
        *(float4*)(sB + l * 16 + q) = *(const float4*)(BCb + l * 32 + q);
        *(float4*)(sC + l * 16 + q) = *(const float4*)(BCb + l * 32 + 16 + q);
    }

    // initial h: sequential combine over preceding chunk carries (float4)
    float h[4] = {0.f, 0.f, 0.f, 0.f};
    {
        const size_t base = ((size_t)b * NCH * DD + d) * NN + n0;
        for (int c = 0; c < ch; c++) {
            const size_t o = base + (size_t)c * (DD * NN);
            const float4 A4 = *(const float4*)(cA + o);
            const float4 H4 = *(const float4*)(cH + o);
            h[0] = fmaf(A4.x, h[0], H4.x);
            h[1] = fmaf(A4.y, h[1], H4.y);
            h[2] = fmaf(A4.z, h[2], H4.z);
            h[3] = fmaf(A4.w, h[3], H4.w);
        }
    }

    float Ac2[4];
#pragma unroll
    for (int j = 0; j < 4; j++)
        Ac2[j] = -__expf(A_log[d * NN + n0 + j]) * LOG2E;

    __syncthreads();

#pragma unroll 4
    for (int l = 0; l < CL; l++) {
        const float dtv = sdt[l * SC_D + dl];
        const float dtx = dtv * sx[l * SC_D + dl];
        const float4 B4 = *(const float4*)(sB + l * 16 + n0);
        const float4 C4 = *(const float4*)(sC + l * 16 + n0);
        float a0 = ex2f(dtv * Ac2[0]);
        float a1 = ex2f(dtv * Ac2[1]);
        float a2 = ex2f(dtv * Ac2[2]);
        float a3 = ex2f(dtv * Ac2[3]);
        h[0] = fmaf(a0, h[0], dtx * B4.x);
        h[1] = fmaf(a1, h[1], dtx * B4.y);
        h[2] = fmaf(a2, h[2], dtx * B4.z);
        h[3] = fmaf(a3, h[3], dtx * B4.w);
        float p01 = fmaf(C4.y, h[1], C4.x * h[0]);
        float p23 = fmaf(C4.w, h[3], C4.z * h[2]);
        float p = p01 + p23;
        p += __shfl_xor_sync(0xffffffffu, p, 1, 4);
        p += __shfl_xor_sync(0xffffffffu, p, 2, 4);
        if (n0 == 0) sY[l * SC_D + dl] = p;
    }
    __syncthreads();

    // cooperative writeback with deferred D-skip + GELU
#pragma unroll
    for (int i = 0; i < 4; i++) {
        int idx = tid + 128 * i;
        int l = idx >> 3;
        int q = (idx & 7) * 4;
        const float4 dk = *(const float4*)(Dskip + d0 + q);
        const float4 xv = *(const float4*)(sx + l * SC_D + q);
        const float4 pv = *(const float4*)(sY + l * SC_D + q);
        float4 o;
        o.x = gelu_f(fmaf(dk.x, xv.x, pv.x));
        o.y = gelu_f(fmaf(dk.y, xv.y, pv.y));
        o.z = gelu_f(fmaf(dk.z, xv.z, pv.z));
        o.w = gelu_f(fmaf(dk.w, xv.w, pv.w));
        *(float4*)(Yb + (size_t)l * DD + d0 + q) = o;
    }
}

// ---------------- layernorm + residual: one warp per row ----------------
// block = 256 = 8 warps = 8 rows; pure warp-shuffle reduction.
__global__ void __launch_bounds__(256)
ln_res_kernel(const float* __restrict__ Hin,
              const float* __restrict__ Y2,
              const float* __restrict__ g,
              const float* __restrict__ bb,
              float* __restrict__ Hout) {
    const int lane = threadIdx.x & 31;
    const int wrp  = threadIdx.x >> 5;
    const int row  = blockIdx.x * 8 + wrp;
    const float* yr = Y2 + (size_t)row * DD;

    float4 v[4];
    float s = 0.f;
#pragma unroll
    for (int j = 0; j < 4; j++) {
        v[j] = *(const float4*)(yr + lane * 4 + j * 128);
        s += (v[j].x + v[j].y) + (v[j].z + v[j].w);
    }
#pragma unroll
    for (int o = 16; o > 0; o >>= 1) s += __shfl_xor_sync(0xffffffffu, s, o);
    const float mean = s * (1.f / DD);

    float sq = 0.f;
#pragma unroll
    for (int j = 0; j < 4; j++) {
        float d0 = v[j].x - mean, d1 = v[j].y - mean;
        float d2 = v[j].z - mean, d3 = v[j].w - mean;
        sq += (d0 * d0 + d1 * d1) + (d2 * d2 + d3 * d3);
    }
#pragma unroll
    for (int o = 16; o > 0; o >>= 1) sq += __shfl_xor_sync(0xffffffffu, sq, o);
    const float rstd = rsqrtf(sq * (1.f / DD) + 1e-5f);

#pragma unroll
    for (int j = 0; j < 4; j++) {
        const int col = lane * 4 + j * 128;
        const float4 gg = *(const float4*)(g + col);
        const float4 bv = *(const float4*)(bb + col);
        const float4 hi = *(const float4*)(Hin + (size_t)row * DD + col);
        float4 o;
        o.x = hi.x + (v[j].x - mean) * rstd * gg.x + bv.x;
        o.y = hi.y + (v[j].y - mean) * rstd * gg.y + bv.y;
        o.z = hi.z + (v[j].z - mean) * rstd * gg.z + bv.z;
        o.w = hi.w + (v[j].w - mean) * rstd * gg.w + bv.w;
        *(float4*)(Hout + (size_t)row * DD + col) = o;
    }
}

// ---------------- launch ----------------
extern "C" void kernel_launch(void* const* d_in, const int* in_sizes, int n_in,
                              void* d_out, int out_size) {
    const float* x      = (const float*)d_in[0];
    const float* A_log  = (const float*)d_in[1];
    const float* W_B    = (const float*)d_in[2];
    const float* b_B    = (const float*)d_in[3];
    const float* W_C    = (const float*)d_in[4];
    const float* b_C    = (const float*)d_in[5];
    const float* W_dt   = (const float*)d_in[6];
    const float* b_dt   = (const float*)d_in[7];
    const float* D_skip = (const float*)d_in[8];
    const float* W_mix  = (const float*)d_in[9];
    const float* b_mix  = (const float*)d_in[10];
    const float* ln_g   = (const float*)d_in[11];
    const float* ln_b   = (const float*)d_in[12];
    const float* W_dec  = (const float*)d_in[13];
    const float* b_dec  = (const float*)d_in[14];
    float* out = (float*)d_out;

    float *p_dt, *p_bc, *p_y, *p_y2, *p_hA, *p_hB, *p_cA, *p_cH;
    cudaGetSymbolAddress((void**)&p_dt, g_dt);
    cudaGetSymbolAddress((void**)&p_bc, g_bc);
    cudaGetSymbolAddress((void**)&p_y,  g_y);
    cudaGetSymbolAddress((void**)&p_y2, g_y2);
    cudaGetSymbolAddress((void**)&p_hA, g_hA);
    cudaGetSymbolAddress((void**)&p_hB, g_hB);
    cudaGetSymbolAddress((void**)&p_cA, g_cA);
    cudaGetSymbolAddress((void**)&p_cH, g_cH);

    cudaFuncSetAttribute(gemm_tc<0>, cudaFuncAttributeMaxDynamicSharedMemorySize,
                         GEMM_SMEM_BYTES);
    cudaFuncSetAttribute(gemm_tc<1>, cudaFuncAttributeMaxDynamicSharedMemorySize,
                         GEMM_SMEM_BYTES);
    cudaFuncSetAttribute(bc_kernel, cudaFuncAttributeMaxDynamicSharedMemorySize,
                         BC_SMEM_BYTES);
    cudaFuncSetAttribute(scan_apply, cudaFuncAttributeMaxDynamicSharedMemorySize,
                         SCAN_SMEM_BYTES);

    const dim3 gemmGrid(DD / 64, MM / 128);       // (8, 64)
    const dim3 scanGrid(DD / SC_D, NCH, BB);      // (16, 32, 4)

    const float* hin = x;
    float* houts[2] = { p_hA, p_hB };

    for (int l = 0; l < NLAYERS; l++) {
        gemm_tc<1><<<gemmGrid, 256, GEMM_SMEM_BYTES>>>(
            hin, W_dt + (size_t)l * DD * DD, b_dt + l * DD, p_dt);
        bc_kernel<<<MM / 32, 256, BC_SMEM_BYTES>>>(
            hin, W_B + (size_t)l * DD * NN, b_B + l * NN,
            W_C + (size_t)l * DD * NN, b_C + l * NN, p_bc);
        scan_carry<<<scanGrid, 128>>>(hin, p_dt, p_bc,
                                      A_log + (size_t)l * DD * NN, p_cA, p_cH);
        scan_apply<<<scanGrid, 128, SCAN_SMEM_BYTES>>>(
            hin, p_dt, p_bc, A_log + (size_t)l * DD * NN,
            D_skip + l * DD, p_cA, p_cH, p_y);
        gemm_tc<0><<<gemmGrid, 256, GEMM_SMEM_BYTES>>>(
            p_y, W_mix + (size_t)l * DD * DD, b_mix + l * DD, p_y2);
        ln_res_kernel<<<MM / 8, 256>>>(hin, p_y2, ln_g + l * DD, ln_b + l * DD,
                                       houts[l]);
        hin = houts[l];
    }

    gemm_tc<0><<<gemmGrid, 256, GEMM_SMEM_BYTES>>>(hin, W_dec, b_dec, out);
}